// round 1
// baseline (speedup 1.0000x reference)
#include <cuda_runtime.h>
#include <math.h>
#include <stddef.h>

#define BB 4
#define SS 2048
#define DM 768
#define NH 8
#define DH 96
#define DFF 3072
#define MM (BB*SS)   /* 8192 rows */

// ---------------- scratch (device globals: allocation-free) ----------------
__device__ float g_q[MM*DM];
__device__ float g_k[MM*DM];
__device__ float g_v[MM*DM];
__device__ float g_ctx[MM*DM];
__device__ float g_t1[MM*DM];
__device__ float g_src2[MM*DM];
__device__ float g_ffh[(size_t)MM*DFF];

// ---------------- GEMM: C[M,N] = A[M,K] @ B[N,K]^T + bias (opt GELU) ------
// BM=BN=128, BK=8, 256 threads, 8x8 microtile.
template<int ACT>
__global__ void __launch_bounds__(256) gemm_nt(
    const float* __restrict__ A, const float* __restrict__ B,
    const float* __restrict__ bias, float* __restrict__ C,
    int M, int N, int K)
{
    const int BM = 128, BN = 128, BK = 8;
    __shared__ float As[BK][BM];
    __shared__ float Bs[BK][BN];

    int tid = threadIdx.x;
    int tx = tid & 15;      // 0..15 -> n microtile
    int ty = tid >> 4;      // 0..15 -> m microtile

    const float* Ab = A + (size_t)blockIdx.y * BM * K;
    const float* Bb = B + (size_t)blockIdx.x * BN * K;

    // loader mapping: each thread loads one float4 of A and one of B per tile
    int lr = tid >> 1;            // row within 128-row tile
    int lc = (tid & 1) * 4;       // col offset 0 or 4 within BK=8

    float acc[8][8];
    #pragma unroll
    for (int i = 0; i < 8; i++)
        #pragma unroll
        for (int j = 0; j < 8; j++) acc[i][j] = 0.f;

    for (int k0 = 0; k0 < K; k0 += BK) {
        float4 av = *(const float4*)(Ab + (size_t)lr * K + k0 + lc);
        float4 bv = *(const float4*)(Bb + (size_t)lr * K + k0 + lc);
        __syncthreads();
        As[lc + 0][lr] = av.x; As[lc + 1][lr] = av.y;
        As[lc + 2][lr] = av.z; As[lc + 3][lr] = av.w;
        Bs[lc + 0][lr] = bv.x; Bs[lc + 1][lr] = bv.y;
        Bs[lc + 2][lr] = bv.z; Bs[lc + 3][lr] = bv.w;
        __syncthreads();

        #pragma unroll
        for (int kk = 0; kk < BK; kk++) {
            float a[8], b[8];
            #pragma unroll
            for (int i = 0; i < 8; i++) a[i] = As[kk][ty * 8 + i];
            #pragma unroll
            for (int j = 0; j < 8; j++) b[j] = Bs[kk][tx * 8 + j];
            #pragma unroll
            for (int i = 0; i < 8; i++)
                #pragma unroll
                for (int j = 0; j < 8; j++)
                    acc[i][j] = fmaf(a[i], b[j], acc[i][j]);
        }
    }

    #pragma unroll
    for (int i = 0; i < 8; i++) {
        int m = blockIdx.y * BM + ty * 8 + i;
        #pragma unroll
        for (int j = 0; j < 8; j++) {
            int n = blockIdx.x * BN + tx * 8 + j;
            float c = acc[i][j] + bias[n];
            if (ACT == 1)
                c = 0.5f * c * (1.0f + erff(c * 0.70710678118654752f));
            C[(size_t)m * N + n] = c;
        }
    }
}

// ---------------- 3D RoPE on q,k in-place ([M, D] layout) ------------------
__global__ void rope_kernel(float* __restrict__ q, float* __restrict__ k,
                            const float* __restrict__ coords)
{
    int idx = blockIdx.x * blockDim.x + threadIdx.x;
    const int total = MM * NH * 16 * 3;
    if (idx >= total) return;
    int axis = idx % 3;
    int j    = (idx / 3) % 16;
    int h    = (idx / 48) % NH;
    int m    = idx / (48 * NH);

    float theta = powf(10000.0f, -(float)j / 16.0f);
    float ang = coords[(size_t)m * 3 + axis] * theta;
    float c = cosf(ang), sn = sinf(ang);

    size_t base = (size_t)m * DM + h * DH + j * 6 + axis * 2;
    float q0 = q[base], q1 = q[base + 1];
    q[base]     = q0 * c - q1 * sn;
    q[base + 1] = q0 * sn + q1 * c;
    float k0 = k[base], k1 = k[base + 1];
    k[base]     = k0 * c - k1 * sn;
    k[base + 1] = k0 * sn + k1 * c;
}

// ---------------- flash attention (fp32, online softmax) -------------------
// grid (S/TQ, H, B), 256 threads. TQ=TK=64.
// smem: Qs[64][96], KV buffer shared between Kst[96][65] and Vs[64][96],
//       Ps[64][65], mi/li/fac[64].
#define TQ 64
#define TK 64
__global__ void __launch_bounds__(256) attn_kernel(
    const float* __restrict__ q, const float* __restrict__ k,
    const float* __restrict__ v, float* __restrict__ ctx)
{
    extern __shared__ float sm[];
    float* Qs  = sm;                      // 64*96 = 6144
    float* KV  = Qs + TQ * DH;            // max(96*65, 64*96) = 6240
    float* Ps  = KV + 96 * 65;            // 64*65 = 4160
    float* mi  = Ps + TQ * 65;            // 64
    float* li  = mi + TQ;                 // 64
    float* fac = li + TQ;                 // 64

    int q0 = blockIdx.x * TQ;
    int h  = blockIdx.y;
    int b  = blockIdx.z;
    int tid = threadIdx.x;
    int tx = tid & 15;    // d / k microtile
    int ty = tid >> 4;    // q microtile

    // load Q tile
    for (int i = tid; i < TQ * DH; i += 256) {
        int r = i / DH, d = i % DH;
        Qs[r * DH + d] = q[((size_t)(b * SS + q0 + r)) * DM + h * DH + d];
    }
    if (tid < TQ) { mi[tid] = -1e30f; li[tid] = 0.f; }
    __syncthreads();

    const float scale = 1.0f / sqrtf((float)DH);
    float acc[4][6];
    #pragma unroll
    for (int i = 0; i < 4; i++)
        #pragma unroll
        for (int j = 0; j < 6; j++) acc[i][j] = 0.f;

    for (int k0 = 0; k0 < SS; k0 += TK) {
        // load K tile transposed: Kst[d][kk], stride 65
        for (int i = tid; i < TK * DH; i += 256) {
            int r = i / DH, d = i % DH;
            KV[d * 65 + r] = k[((size_t)(b * SS + k0 + r)) * DM + h * DH + d];
        }
        __syncthreads();

        // scores: 4q x 4k per thread
        float s4[4][4];
        #pragma unroll
        for (int i = 0; i < 4; i++)
            #pragma unroll
            for (int j = 0; j < 4; j++) s4[i][j] = 0.f;
        for (int dd = 0; dd < DH; dd++) {
            float aq[4], bk[4];
            #pragma unroll
            for (int i = 0; i < 4; i++) aq[i] = Qs[(ty * 4 + i) * DH + dd];
            #pragma unroll
            for (int j = 0; j < 4; j++) bk[j] = KV[dd * 65 + tx * 4 + j];
            #pragma unroll
            for (int i = 0; i < 4; i++)
                #pragma unroll
                for (int j = 0; j < 4; j++)
                    s4[i][j] = fmaf(aq[i], bk[j], s4[i][j]);
        }
        #pragma unroll
        for (int i = 0; i < 4; i++)
            #pragma unroll
            for (int j = 0; j < 4; j++)
                Ps[(ty * 4 + i) * 65 + tx * 4 + j] = s4[i][j] * scale;
        __syncthreads();

        // online softmax per row (threads 0..63)
        if (tid < TQ) {
            float m_old = mi[tid];
            float mx = m_old;
            for (int kk = 0; kk < TK; kk++)
                mx = fmaxf(mx, Ps[tid * 65 + kk]);
            float f = expf(m_old - mx);
            float sum = 0.f;
            for (int kk = 0; kk < TK; kk++) {
                float p = expf(Ps[tid * 65 + kk] - mx);
                Ps[tid * 65 + kk] = p;
                sum += p;
            }
            mi[tid] = mx;
            li[tid] = li[tid] * f + sum;
            fac[tid] = f;
        }
        __syncthreads();

        // rescale accumulators
        #pragma unroll
        for (int i = 0; i < 4; i++) {
            float f = fac[ty * 4 + i];
            #pragma unroll
            for (int j = 0; j < 6; j++) acc[i][j] *= f;
        }

        // load V tile into KV buffer: Vs[kk][d], stride 96
        for (int i = tid; i < TK * DH; i += 256) {
            int r = i / DH, d = i % DH;
            KV[r * DH + d] = v[((size_t)(b * SS + k0 + r)) * DM + h * DH + d];
        }
        __syncthreads();

        // PV: 4q x 6d per thread
        for (int kk = 0; kk < TK; kk++) {
            float pv[4], vv[6];
            #pragma unroll
            for (int i = 0; i < 4; i++) pv[i] = Ps[(ty * 4 + i) * 65 + kk];
            #pragma unroll
            for (int j = 0; j < 6; j++) vv[j] = KV[kk * DH + tx * 6 + j];
            #pragma unroll
            for (int i = 0; i < 4; i++)
                #pragma unroll
                for (int j = 0; j < 6; j++)
                    acc[i][j] = fmaf(pv[i], vv[j], acc[i][j]);
        }
        __syncthreads();   // before next tile overwrites KV / Ps
    }

    // epilogue: normalize by l, write ctx
    #pragma unroll
    for (int i = 0; i < 4; i++) {
        float inv = 1.0f / li[ty * 4 + i];
        size_t m = (size_t)(b * SS + q0 + ty * 4 + i);
        #pragma unroll
        for (int j = 0; j < 6; j++)
            ctx[m * DM + h * DH + tx * 6 + j] = acc[i][j] * inv;
    }
}

// ---------------- residual add + LayerNorm (one block per row) -------------
__device__ __forceinline__ float block_sum256(float val, float* red) {
    #pragma unroll
    for (int o = 16; o > 0; o >>= 1)
        val += __shfl_xor_sync(0xffffffffu, val, o);
    int w = threadIdx.x >> 5;
    if ((threadIdx.x & 31) == 0) red[w] = val;
    __syncthreads();
    if (threadIdx.x < 32) {
        float vv = (threadIdx.x < 8) ? red[threadIdx.x] : 0.f;
        #pragma unroll
        for (int o = 4; o > 0; o >>= 1)
            vv += __shfl_xor_sync(0xffffffffu, vv, o);
        if (threadIdx.x == 0) red[0] = vv;
    }
    __syncthreads();
    float r = red[0];
    __syncthreads();
    return r;
}

__global__ void __launch_bounds__(256) add_ln_kernel(
    const float* __restrict__ x, const float* __restrict__ y,
    const float* __restrict__ g, const float* __restrict__ be,
    float* __restrict__ out)
{
    __shared__ float red[32];
    size_t m = blockIdx.x;
    const float* xr = x + m * DM;
    const float* yr = y + m * DM;

    float v[3];
    float s = 0.f;
    #pragma unroll
    for (int i = 0; i < 3; i++) {
        int d = threadIdx.x + i * 256;
        v[i] = xr[d] + yr[d];
        s += v[i];
    }
    float mean = block_sum256(s, red) * (1.0f / DM);
    float sq = 0.f;
    #pragma unroll
    for (int i = 0; i < 3; i++) {
        float dd = v[i] - mean;
        sq += dd * dd;
    }
    float var = block_sum256(sq, red) * (1.0f / DM);
    float inv = rsqrtf(var + 1e-5f);
    #pragma unroll
    for (int i = 0; i < 3; i++) {
        int d = threadIdx.x + i * 256;
        out[m * DM + d] = (v[i] - mean) * inv * g[d] + be[d];
    }
}

// ---------------- launch ---------------------------------------------------
extern "C" void kernel_launch(void* const* d_in, const int* in_sizes, int n_in,
                              void* d_out, int out_size)
{
    const float* src    = (const float*)d_in[0];
    const float* coords = (const float*)d_in[1];
    const float* Wq = (const float*)d_in[2];
    const float* bq = (const float*)d_in[3];
    const float* Wk = (const float*)d_in[4];
    const float* bk = (const float*)d_in[5];
    const float* Wv = (const float*)d_in[6];
    const float* bv = (const float*)d_in[7];
    const float* Wo = (const float*)d_in[8];
    const float* bo = (const float*)d_in[9];
    const float* W1 = (const float*)d_in[10];
    const float* b1 = (const float*)d_in[11];
    const float* W2 = (const float*)d_in[12];
    const float* b2 = (const float*)d_in[13];
    const float* g1  = (const float*)d_in[14];
    const float* be1 = (const float*)d_in[15];
    const float* g2  = (const float*)d_in[16];
    const float* be2 = (const float*)d_in[17];
    float* out = (float*)d_out;

    float *q, *k, *v, *ctx, *t1, *src2, *ffh;
    cudaGetSymbolAddress((void**)&q,    g_q);
    cudaGetSymbolAddress((void**)&k,    g_k);
    cudaGetSymbolAddress((void**)&v,    g_v);
    cudaGetSymbolAddress((void**)&ctx,  g_ctx);
    cudaGetSymbolAddress((void**)&t1,   g_t1);
    cudaGetSymbolAddress((void**)&src2, g_src2);
    cudaGetSymbolAddress((void**)&ffh,  g_ffh);

    dim3 g768(DM / 128, MM / 128);     // (6, 64)
    dim3 gff(DFF / 128, MM / 128);     // (24, 64)

    // QKV projections
    gemm_nt<0><<<g768, 256>>>(src, Wq, bq, q, MM, DM, DM);
    gemm_nt<0><<<g768, 256>>>(src, Wk, bk, k, MM, DM, DM);
    gemm_nt<0><<<g768, 256>>>(src, Wv, bv, v, MM, DM, DM);

    // RoPE on q, k
    {
        int total = MM * NH * 16 * 3;
        rope_kernel<<<(total + 255) / 256, 256>>>(q, k, coords);
    }

    // attention
    {
        size_t smemb = (size_t)(TQ * DH + 96 * 65 + TQ * 65 + 3 * TQ) * sizeof(float);
        cudaFuncSetAttribute((const void*)attn_kernel,
                             cudaFuncAttributeMaxDynamicSharedMemorySize,
                             (int)smemb);
        attn_kernel<<<dim3(SS / TQ, NH, BB), 256, smemb>>>(q, k, v, ctx);
    }

    // output projection + residual + LN1
    gemm_nt<0><<<g768, 256>>>(ctx, Wo, bo, t1, MM, DM, DM);
    add_ln_kernel<<<MM, 256>>>(src, t1, g1, be1, src2);

    // FFN
    gemm_nt<1><<<gff, 256>>>(src2, W1, b1, ffh, MM, DFF, DM);
    gemm_nt<0><<<g768, 256>>>(ffh, W2, b2, t1, MM, DM, DFF);
    add_ln_kernel<<<MM, 256>>>(src2, t1, g2, be2, out);
}

// round 5
// speedup vs baseline: 1.5373x; 1.5373x over previous
#include <cuda_runtime.h>
#include <cuda_bf16.h>
#include <math.h>
#include <stddef.h>
#include <stdint.h>

#define BB 4
#define SS 2048
#define DM 768
#define NH 8
#define DH 96
#define DFF 3072
#define MM (BB*SS)   /* 8192 rows */

// ---------------- scratch (device globals: allocation-free) ----------------
__device__ float g_q[MM*DM];
__device__ float g_k[MM*DM];
__device__ float g_v[MM*DM];
__device__ float g_ctx[MM*DM];
__device__ float g_t1[MM*DM];
__device__ float g_src2[MM*DM];
__device__ float g_ffh[(size_t)MM*DFF];

// ================= helpers =================================================
static __device__ __forceinline__ uint32_t smem_u32(const void* p) {
    uint32_t a;
    asm("{ .reg .u64 t; cvta.to.shared.u64 t, %1; cvt.u32.u64 %0, t; }"
        : "=r"(a) : "l"(p));
    return a;
}

#define LDSM4(R0,R1,R2,R3,addr) \
    asm volatile("ldmatrix.sync.aligned.m8n8.x4.shared.b16 {%0,%1,%2,%3}, [%4];" \
        : "=r"(R0),"=r"(R1),"=r"(R2),"=r"(R3) : "r"(addr))

#define MMA16816(d, a, b) \
    asm volatile("mma.sync.aligned.m16n8k16.row.col.f32.bf16.bf16.f32 " \
        "{%0,%1,%2,%3}, {%4,%5,%6,%7}, {%8,%9}, {%0,%1,%2,%3};" \
        : "+f"((d)[0]), "+f"((d)[1]), "+f"((d)[2]), "+f"((d)[3]) \
        : "r"((a)[0]), "r"((a)[1]), "r"((a)[2]), "r"((a)[3]), \
          "r"((b)[0]), "r"((b)[1]))

// ============ HMMA GEMM: C[M,N] = A[M,K] @ B[N,K]^T + bias (opt GELU) ======
// 256 threads = 8 warps (2 m x 4 n). CTA tile 128x128, warp tile 64x32, BK=32.
// bf16 hi/lo split: acc += Ahi*Bhi + Ahi*Blo + Alo*Bhi  (fp32 accum).
#define KS 40   /* smem row stride in bf16 elements: conflict-free for ldmatrix */

// convert one float4 to hi/lo bf16x2 pairs and store 8B each
static __device__ __forceinline__ void cvt_store(
    uint16_t* __restrict__ hi, uint16_t* __restrict__ lo, int eoff, float4 a)
{
    __nv_bfloat16 hx = __float2bfloat16_rn(a.x);
    __nv_bfloat16 hy = __float2bfloat16_rn(a.y);
    __nv_bfloat16 hz = __float2bfloat16_rn(a.z);
    __nv_bfloat16 hw = __float2bfloat16_rn(a.w);
    __nv_bfloat162 h0; h0.x = hx; h0.y = hy;
    __nv_bfloat162 h1; h1.x = hz; h1.y = hw;
    __nv_bfloat162 l0 = __floats2bfloat162_rn(a.x - __bfloat162float(hx),
                                              a.y - __bfloat162float(hy));
    __nv_bfloat162 l1 = __floats2bfloat162_rn(a.z - __bfloat162float(hz),
                                              a.w - __bfloat162float(hw));
    uint2 hv; hv.x = *(uint32_t*)&h0; hv.y = *(uint32_t*)&h1;
    uint2 lv; lv.x = *(uint32_t*)&l0; lv.y = *(uint32_t*)&l1;
    *(uint2*)(hi + eoff) = hv;
    *(uint2*)(lo + eoff) = lv;
}

template<int ACT>
__global__ void __launch_bounds__(256) gemm_tc(
    const float* __restrict__ A, const float* __restrict__ B,
    const float* __restrict__ bias, float* __restrict__ C,
    int M, int N, int K)
{
    __shared__ __align__(16) uint16_t As_hi[128*KS];
    __shared__ __align__(16) uint16_t As_lo[128*KS];
    __shared__ __align__(16) uint16_t Bs_hi[128*KS];
    __shared__ __align__(16) uint16_t Bs_lo[128*KS];

    const int tid  = threadIdx.x;
    const int warp = tid >> 5;
    const int lane = tid & 31;
    const int wm   = warp & 1;    // 0..1  (m)
    const int wn   = warp >> 1;   // 0..3  (n)

    const int m0 = blockIdx.y * 128;
    const int n0 = blockIdx.x * 128;
    const float* Ab = A + (size_t)m0 * K;
    const float* Bb = B + (size_t)n0 * K;

    // gmem loader mapping: idx -> (row, col4)
    const int l_row = tid >> 3;        // 0..31 (+32 per pass)
    const int l_c4  = tid & 7;         // float4 column

    // ldmatrix lane addressing (element offsets into [row][col] with stride KS)
    const uint32_t a_hi_base = smem_u32(As_hi);
    const uint32_t a_lo_base = smem_u32(As_lo);
    const uint32_t b_hi_base = smem_u32(Bs_hi);
    const uint32_t b_lo_base = smem_u32(Bs_lo);
    const int a_row  = wm * 64 + (lane & 15);
    const int a_coff = (lane >> 4) * 8;
    const int b_row  = wn * 32 + (lane & 7) + ((lane >> 4) << 3);
    const int b_coff = ((lane >> 3) & 1) * 8;

    float acc[4][4][4];
    #pragma unroll
    for (int mi = 0; mi < 4; mi++)
        #pragma unroll
        for (int ni = 0; ni < 4; ni++)
            #pragma unroll
            for (int r = 0; r < 4; r++) acc[mi][ni][r] = 0.f;

    const int T = K >> 5;
    for (int t = 0; t < T; t++) {
        const int k0 = t << 5;
        float4 av[4], bv[4];
        #pragma unroll
        for (int i = 0; i < 4; i++) {
            av[i] = *(const float4*)(Ab + (size_t)(l_row + i * 32) * K + k0 + l_c4 * 4);
            bv[i] = *(const float4*)(Bb + (size_t)(l_row + i * 32) * K + k0 + l_c4 * 4);
        }
        __syncthreads();   // previous iteration's ldmatrix reads complete
        #pragma unroll
        for (int i = 0; i < 4; i++) {
            int eoff = (l_row + i * 32) * KS + l_c4 * 4;
            cvt_store(As_hi, As_lo, eoff, av[i]);
            cvt_store(Bs_hi, Bs_lo, eoff, bv[i]);
        }
        __syncthreads();

        #pragma unroll
        for (int kh = 0; kh < 2; kh++) {
            const int k16 = kh * 16;
            // B fragments: 2 x4 per precision cover 4 n8-tiles
            uint32_t bh[4][2], bl[4][2];
            #pragma unroll
            for (int p = 0; p < 2; p++) {
                uint32_t off = (uint32_t)((b_row + p * 16) * KS + b_coff + k16) * 2;
                LDSM4(bh[p*2][0], bh[p*2][1], bh[p*2+1][0], bh[p*2+1][1], b_hi_base + off);
                LDSM4(bl[p*2][0], bl[p*2][1], bl[p*2+1][0], bl[p*2+1][1], b_lo_base + off);
            }
            // A hi fragments
            uint32_t a[4][4];
            #pragma unroll
            for (int mi = 0; mi < 4; mi++) {
                uint32_t off = (uint32_t)((a_row + mi * 16) * KS + a_coff + k16) * 2;
                LDSM4(a[mi][0], a[mi][1], a[mi][2], a[mi][3], a_hi_base + off);
            }
            #pragma unroll
            for (int mi = 0; mi < 4; mi++)
                #pragma unroll
                for (int ni = 0; ni < 4; ni++) {
                    MMA16816(acc[mi][ni], a[mi], bh[ni]);
                    MMA16816(acc[mi][ni], a[mi], bl[ni]);
                }
            // A lo fragments (reuse regs)
            #pragma unroll
            for (int mi = 0; mi < 4; mi++) {
                uint32_t off = (uint32_t)((a_row + mi * 16) * KS + a_coff + k16) * 2;
                LDSM4(a[mi][0], a[mi][1], a[mi][2], a[mi][3], a_lo_base + off);
            }
            #pragma unroll
            for (int mi = 0; mi < 4; mi++)
                #pragma unroll
                for (int ni = 0; ni < 4; ni++)
                    MMA16816(acc[mi][ni], a[mi], bh[ni]);
        }
    }

    // epilogue: direct stores (float2 per lane-quad = 32B contiguous segments)
    const int er = lane >> 2;
    const int ec = (lane & 3) * 2;
    #pragma unroll
    for (int mi = 0; mi < 4; mi++) {
        #pragma unroll
        for (int ni = 0; ni < 4; ni++) {
            int row = m0 + wm * 64 + mi * 16 + er;
            int col = n0 + wn * 32 + ni * 8 + ec;
            float b0 = bias[col], b1 = bias[col + 1];
            #pragma unroll
            for (int half = 0; half < 2; half++) {
                float x = acc[mi][ni][half * 2 + 0] + b0;
                float y = acc[mi][ni][half * 2 + 1] + b1;
                if (ACT == 1) {
                    x = 0.5f * x * (1.0f + erff(x * 0.70710678118654752f));
                    y = 0.5f * y * (1.0f + erff(y * 0.70710678118654752f));
                }
                float2 o; o.x = x; o.y = y;
                *(float2*)(C + (size_t)(row + half * 8) * N + col) = o;
            }
        }
    }
}

// ---------------- 3D RoPE on q,k in-place ([M, D] layout) ------------------
__global__ void rope_kernel(float* __restrict__ q, float* __restrict__ k,
                            const float* __restrict__ coords)
{
    int idx = blockIdx.x * blockDim.x + threadIdx.x;
    const int total = MM * NH * 16 * 3;
    if (idx >= total) return;
    int axis = idx % 3;
    int j    = (idx / 3) % 16;
    int h    = (idx / 48) % NH;
    int m    = idx / (48 * NH);

    float theta = powf(10000.0f, -(float)j / 16.0f);
    float ang = coords[(size_t)m * 3 + axis] * theta;
    float c = cosf(ang), sn = sinf(ang);

    size_t base = (size_t)m * DM + h * DH + j * 6 + axis * 2;
    float q0 = q[base], q1 = q[base + 1];
    q[base]     = q0 * c - q1 * sn;
    q[base + 1] = q0 * sn + q1 * c;
    float k0 = k[base], k1 = k[base + 1];
    k[base]     = k0 * c - k1 * sn;
    k[base + 1] = k0 * sn + k1 * c;
}

// ---------------- flash attention (fp32, online softmax) -------------------
#define TQ 64
#define TK 64
__global__ void __launch_bounds__(256) attn_kernel(
    const float* __restrict__ q, const float* __restrict__ k,
    const float* __restrict__ v, float* __restrict__ ctx)
{
    extern __shared__ float sm[];
    float* Qs  = sm;
    float* KV  = Qs + TQ * DH;
    float* Ps  = KV + 96 * 65;
    float* mi  = Ps + TQ * 65;
    float* li  = mi + TQ;
    float* fac = li + TQ;

    int q0 = blockIdx.x * TQ;
    int h  = blockIdx.y;
    int b  = blockIdx.z;
    int tid = threadIdx.x;
    int tx = tid & 15;
    int ty = tid >> 4;

    for (int i = tid; i < TQ * DH; i += 256) {
        int r = i / DH, d = i % DH;
        Qs[r * DH + d] = q[((size_t)(b * SS + q0 + r)) * DM + h * DH + d];
    }
    if (tid < TQ) { mi[tid] = -1e30f; li[tid] = 0.f; }
    __syncthreads();

    const float scale = 1.0f / sqrtf((float)DH);
    float acc[4][6];
    #pragma unroll
    for (int i = 0; i < 4; i++)
        #pragma unroll
        for (int j = 0; j < 6; j++) acc[i][j] = 0.f;

    for (int k0 = 0; k0 < SS; k0 += TK) {
        for (int i = tid; i < TK * DH; i += 256) {
            int r = i / DH, d = i % DH;
            KV[d * 65 + r] = k[((size_t)(b * SS + k0 + r)) * DM + h * DH + d];
        }
        __syncthreads();

        float s4[4][4];
        #pragma unroll
        for (int i = 0; i < 4; i++)
            #pragma unroll
            for (int j = 0; j < 4; j++) s4[i][j] = 0.f;
        for (int dd = 0; dd < DH; dd++) {
            float aq[4], bk[4];
            #pragma unroll
            for (int i = 0; i < 4; i++) aq[i] = Qs[(ty * 4 + i) * DH + dd];
            #pragma unroll
            for (int j = 0; j < 4; j++) bk[j] = KV[dd * 65 + tx * 4 + j];
            #pragma unroll
            for (int i = 0; i < 4; i++)
                #pragma unroll
                for (int j = 0; j < 4; j++)
                    s4[i][j] = fmaf(aq[i], bk[j], s4[i][j]);
        }
        #pragma unroll
        for (int i = 0; i < 4; i++)
            #pragma unroll
            for (int j = 0; j < 4; j++)
                Ps[(ty * 4 + i) * 65 + tx * 4 + j] = s4[i][j] * scale;
        __syncthreads();

        if (tid < TQ) {
            float m_old = mi[tid];
            float mx = m_old;
            for (int kk = 0; kk < TK; kk++)
                mx = fmaxf(mx, Ps[tid * 65 + kk]);
            float f = expf(m_old - mx);
            float sum = 0.f;
            for (int kk = 0; kk < TK; kk++) {
                float p = expf(Ps[tid * 65 + kk] - mx);
                Ps[tid * 65 + kk] = p;
                sum += p;
            }
            mi[tid] = mx;
            li[tid] = li[tid] * f + sum;
            fac[tid] = f;
        }
        __syncthreads();

        #pragma unroll
        for (int i = 0; i < 4; i++) {
            float f = fac[ty * 4 + i];
            #pragma unroll
            for (int j = 0; j < 6; j++) acc[i][j] *= f;
        }

        for (int i = tid; i < TK * DH; i += 256) {
            int r = i / DH, d = i % DH;
            KV[r * DH + d] = v[((size_t)(b * SS + k0 + r)) * DM + h * DH + d];
        }
        __syncthreads();

        for (int kk = 0; kk < TK; kk++) {
            float pv[4], vv[6];
            #pragma unroll
            for (int i = 0; i < 4; i++) pv[i] = Ps[(ty * 4 + i) * 65 + kk];
            #pragma unroll
            for (int j = 0; j < 6; j++) vv[j] = KV[kk * DH + tx * 6 + j];
            #pragma unroll
            for (int i = 0; i < 4; i++)
                #pragma unroll
                for (int j = 0; j < 6; j++)
                    acc[i][j] = fmaf(pv[i], vv[j], acc[i][j]);
        }
        __syncthreads();
    }

    #pragma unroll
    for (int i = 0; i < 4; i++) {
        float inv = 1.0f / li[ty * 4 + i];
        size_t m = (size_t)(b * SS + q0 + ty * 4 + i);
        #pragma unroll
        for (int j = 0; j < 6; j++)
            ctx[m * DM + h * DH + tx * 6 + j] = acc[i][j] * inv;
    }
}

// ---------------- residual add + LayerNorm (one block per row) -------------
__device__ __forceinline__ float block_sum256(float val, float* red) {
    #pragma unroll
    for (int o = 16; o > 0; o >>= 1)
        val += __shfl_xor_sync(0xffffffffu, val, o);
    int w = threadIdx.x >> 5;
    if ((threadIdx.x & 31) == 0) red[w] = val;
    __syncthreads();
    if (threadIdx.x < 32) {
        float vv = (threadIdx.x < 8) ? red[threadIdx.x] : 0.f;
        #pragma unroll
        for (int o = 4; o > 0; o >>= 1)
            vv += __shfl_xor_sync(0xffffffffu, vv, o);
        if (threadIdx.x == 0) red[0] = vv;
    }
    __syncthreads();
    float r = red[0];
    __syncthreads();
    return r;
}

__global__ void __launch_bounds__(256) add_ln_kernel(
    const float* __restrict__ x, const float* __restrict__ y,
    const float* __restrict__ g, const float* __restrict__ be,
    float* __restrict__ out)
{
    __shared__ float red[32];
    size_t m = blockIdx.x;
    const float* xr = x + m * DM;
    const float* yr = y + m * DM;

    float v[3];
    float s = 0.f;
    #pragma unroll
    for (int i = 0; i < 3; i++) {
        int d = threadIdx.x + i * 256;
        v[i] = xr[d] + yr[d];
        s += v[i];
    }
    float mean = block_sum256(s, red) * (1.0f / DM);
    float sq = 0.f;
    #pragma unroll
    for (int i = 0; i < 3; i++) {
        float dd = v[i] - mean;
        sq += dd * dd;
    }
    float var = block_sum256(sq, red) * (1.0f / DM);
    float inv = rsqrtf(var + 1e-5f);
    #pragma unroll
    for (int i = 0; i < 3; i++) {
        int d = threadIdx.x + i * 256;
        out[m * DM + d] = (v[i] - mean) * inv * g[d] + be[d];
    }
}

// ---------------- launch ---------------------------------------------------
extern "C" void kernel_launch(void* const* d_in, const int* in_sizes, int n_in,
                              void* d_out, int out_size)
{
    const float* src    = (const float*)d_in[0];
    const float* coords = (const float*)d_in[1];
    const float* Wq = (const float*)d_in[2];
    const float* bq = (const float*)d_in[3];
    const float* Wk = (const float*)d_in[4];
    const float* bk = (const float*)d_in[5];
    const float* Wv = (const float*)d_in[6];
    const float* bv = (const float*)d_in[7];
    const float* Wo = (const float*)d_in[8];
    const float* bo = (const float*)d_in[9];
    const float* W1 = (const float*)d_in[10];
    const float* b1 = (const float*)d_in[11];
    const float* W2 = (const float*)d_in[12];
    const float* b2 = (const float*)d_in[13];
    const float* g1  = (const float*)d_in[14];
    const float* be1 = (const float*)d_in[15];
    const float* g2  = (const float*)d_in[16];
    const float* be2 = (const float*)d_in[17];
    float* out = (float*)d_out;

    float *q, *k, *v, *ctx, *t1, *src2, *ffh;
    cudaGetSymbolAddress((void**)&q,    g_q);
    cudaGetSymbolAddress((void**)&k,    g_k);
    cudaGetSymbolAddress((void**)&v,    g_v);
    cudaGetSymbolAddress((void**)&ctx,  g_ctx);
    cudaGetSymbolAddress((void**)&t1,   g_t1);
    cudaGetSymbolAddress((void**)&src2, g_src2);
    cudaGetSymbolAddress((void**)&ffh,  g_ffh);

    dim3 g768(DM / 128, MM / 128);     // (6, 64)
    dim3 gff(DFF / 128, MM / 128);     // (24, 64)

    // QKV projections (HMMA bf16 hi/lo split)
    gemm_tc<0><<<g768, 256>>>(src, Wq, bq, q, MM, DM, DM);
    gemm_tc<0><<<g768, 256>>>(src, Wk, bk, k, MM, DM, DM);
    gemm_tc<0><<<g768, 256>>>(src, Wv, bv, v, MM, DM, DM);

    // RoPE on q, k
    {
        int total = MM * NH * 16 * 3;
        rope_kernel<<<(total + 255) / 256, 256>>>(q, k, coords);
    }

    // attention
    {
        size_t smemb = (size_t)(TQ * DH + 96 * 65 + TQ * 65 + 3 * TQ) * sizeof(float);
        cudaFuncSetAttribute((const void*)attn_kernel,
                             cudaFuncAttributeMaxDynamicSharedMemorySize,
                             (int)smemb);
        attn_kernel<<<dim3(SS / TQ, NH, BB), 256, smemb>>>(q, k, v, ctx);
    }

    // output projection + residual + LN1
    gemm_tc<0><<<g768, 256>>>(ctx, Wo, bo, t1, MM, DM, DM);
    add_ln_kernel<<<MM, 256>>>(src, t1, g1, be1, src2);

    // FFN
    gemm_tc<1><<<gff, 256>>>(src2, W1, b1, ffh, MM, DFF, DM);
    gemm_tc<0><<<g768, 256>>>(ffh, W2, b2, t1, MM, DM, DFF);
    add_ln_kernel<<<MM, 256>>>(src2, t1, g2, be2, out);
}

// round 7
// speedup vs baseline: 1.8476x; 1.2018x over previous
#include <cuda_runtime.h>
#include <cuda_bf16.h>
#include <math.h>
#include <stddef.h>
#include <stdint.h>

#define BB 4
#define SS 2048
#define DM 768
#define NH 8
#define DH 96
#define DFF 3072
#define MM (BB*SS)   /* 8192 rows */

// ---------------- scratch (device globals: allocation-free) ----------------
__device__ float g_q[MM*DM];
__device__ float g_k[MM*DM];
__device__ float g_v[MM*DM];
__device__ float g_ctx[MM*DM];
__device__ float g_t1[MM*DM];
__device__ float g_src2[MM*DM];
__device__ float g_ffh[(size_t)MM*DFF];

// ================= helpers =================================================
static __device__ __forceinline__ uint32_t smem_u32(const void* p) {
    uint32_t a;
    asm("{ .reg .u64 t; cvta.to.shared.u64 t, %1; cvt.u32.u64 %0, t; }"
        : "=r"(a) : "l"(p));
    return a;
}

#define LDSM4(R0,R1,R2,R3,addr) \
    asm volatile("ldmatrix.sync.aligned.m8n8.x4.shared.b16 {%0,%1,%2,%3}, [%4];" \
        : "=r"(R0),"=r"(R1),"=r"(R2),"=r"(R3) : "r"(addr))

#define MMA16816(d, a, b) \
    asm volatile("mma.sync.aligned.m16n8k16.row.col.f32.bf16.bf16.f32 " \
        "{%0,%1,%2,%3}, {%4,%5,%6,%7}, {%8,%9}, {%0,%1,%2,%3};" \
        : "+f"((d)[0]), "+f"((d)[1]), "+f"((d)[2]), "+f"((d)[3]) \
        : "r"((a)[0]), "r"((a)[1]), "r"((a)[2]), "r"((a)[3]), \
          "r"((b)[0]), "r"((b)[1]))

// convert one float4 to hi/lo bf16x2 pairs and store 8B each
static __device__ __forceinline__ void cvt_store(
    uint16_t* __restrict__ hi, uint16_t* __restrict__ lo, int eoff, float4 a)
{
    __nv_bfloat16 hx = __float2bfloat16_rn(a.x);
    __nv_bfloat16 hy = __float2bfloat16_rn(a.y);
    __nv_bfloat16 hz = __float2bfloat16_rn(a.z);
    __nv_bfloat16 hw = __float2bfloat16_rn(a.w);
    __nv_bfloat162 h0; h0.x = hx; h0.y = hy;
    __nv_bfloat162 h1; h1.x = hz; h1.y = hw;
    __nv_bfloat162 l0 = __floats2bfloat162_rn(a.x - __bfloat162float(hx),
                                              a.y - __bfloat162float(hy));
    __nv_bfloat162 l1 = __floats2bfloat162_rn(a.z - __bfloat162float(hz),
                                              a.w - __bfloat162float(hw));
    uint2 hv; hv.x = *(uint32_t*)&h0; hv.y = *(uint32_t*)&h1;
    uint2 lv; lv.x = *(uint32_t*)&l0; lv.y = *(uint32_t*)&l1;
    *(uint2*)(hi + eoff) = hv;
    *(uint2*)(lo + eoff) = lv;
}

// ============ HMMA GEMM: C[M,N] = A[M,K] @ B[N,K]^T + bias (opt GELU) ======
#define KS 40

template<int ACT>
__global__ void __launch_bounds__(256) gemm_tc(
    const float* __restrict__ A, const float* __restrict__ B,
    const float* __restrict__ bias, float* __restrict__ C,
    int M, int N, int K)
{
    __shared__ __align__(16) uint16_t As_hi[128*KS];
    __shared__ __align__(16) uint16_t As_lo[128*KS];
    __shared__ __align__(16) uint16_t Bs_hi[128*KS];
    __shared__ __align__(16) uint16_t Bs_lo[128*KS];

    const int tid  = threadIdx.x;
    const int warp = tid >> 5;
    const int lane = tid & 31;
    const int wm   = warp & 1;
    const int wn   = warp >> 1;

    const int m0 = blockIdx.y * 128;
    const int n0 = blockIdx.x * 128;
    const float* Ab = A + (size_t)m0 * K;
    const float* Bb = B + (size_t)n0 * K;

    const int l_row = tid >> 3;
    const int l_c4  = tid & 7;

    const uint32_t a_hi_base = smem_u32(As_hi);
    const uint32_t a_lo_base = smem_u32(As_lo);
    const uint32_t b_hi_base = smem_u32(Bs_hi);
    const uint32_t b_lo_base = smem_u32(Bs_lo);
    const int a_row  = wm * 64 + (lane & 15);
    const int a_coff = (lane >> 4) * 8;
    const int b_row  = wn * 32 + (lane & 7) + ((lane >> 4) << 3);
    const int b_coff = ((lane >> 3) & 1) * 8;

    float acc[4][4][4];
    #pragma unroll
    for (int mi = 0; mi < 4; mi++)
        #pragma unroll
        for (int ni = 0; ni < 4; ni++)
            #pragma unroll
            for (int r = 0; r < 4; r++) acc[mi][ni][r] = 0.f;

    const int T = K >> 5;
    for (int t = 0; t < T; t++) {
        const int k0 = t << 5;
        float4 av[4], bv[4];
        #pragma unroll
        for (int i = 0; i < 4; i++) {
            av[i] = *(const float4*)(Ab + (size_t)(l_row + i * 32) * K + k0 + l_c4 * 4);
            bv[i] = *(const float4*)(Bb + (size_t)(l_row + i * 32) * K + k0 + l_c4 * 4);
        }
        __syncthreads();
        #pragma unroll
        for (int i = 0; i < 4; i++) {
            int eoff = (l_row + i * 32) * KS + l_c4 * 4;
            cvt_store(As_hi, As_lo, eoff, av[i]);
            cvt_store(Bs_hi, Bs_lo, eoff, bv[i]);
        }
        __syncthreads();

        #pragma unroll
        for (int kh = 0; kh < 2; kh++) {
            const int k16 = kh * 16;
            uint32_t bh[4][2], bl[4][2];
            #pragma unroll
            for (int p = 0; p < 2; p++) {
                uint32_t off = (uint32_t)((b_row + p * 16) * KS + b_coff + k16) * 2;
                LDSM4(bh[p*2][0], bh[p*2][1], bh[p*2+1][0], bh[p*2+1][1], b_hi_base + off);
                LDSM4(bl[p*2][0], bl[p*2][1], bl[p*2+1][0], bl[p*2+1][1], b_lo_base + off);
            }
            uint32_t a[4][4];
            #pragma unroll
            for (int mi = 0; mi < 4; mi++) {
                uint32_t off = (uint32_t)((a_row + mi * 16) * KS + a_coff + k16) * 2;
                LDSM4(a[mi][0], a[mi][1], a[mi][2], a[mi][3], a_hi_base + off);
            }
            #pragma unroll
            for (int mi = 0; mi < 4; mi++)
                #pragma unroll
                for (int ni = 0; ni < 4; ni++) {
                    MMA16816(acc[mi][ni], a[mi], bh[ni]);
                    MMA16816(acc[mi][ni], a[mi], bl[ni]);
                }
            #pragma unroll
            for (int mi = 0; mi < 4; mi++) {
                uint32_t off = (uint32_t)((a_row + mi * 16) * KS + a_coff + k16) * 2;
                LDSM4(a[mi][0], a[mi][1], a[mi][2], a[mi][3], a_lo_base + off);
            }
            #pragma unroll
            for (int mi = 0; mi < 4; mi++)
                #pragma unroll
                for (int ni = 0; ni < 4; ni++)
                    MMA16816(acc[mi][ni], a[mi], bh[ni]);
        }
    }

    const int er = lane >> 2;
    const int ec = (lane & 3) * 2;
    #pragma unroll
    for (int mi = 0; mi < 4; mi++) {
        #pragma unroll
        for (int ni = 0; ni < 4; ni++) {
            int row = m0 + wm * 64 + mi * 16 + er;
            int col = n0 + wn * 32 + ni * 8 + ec;
            float b0 = bias[col], b1 = bias[col + 1];
            #pragma unroll
            for (int half = 0; half < 2; half++) {
                float x = acc[mi][ni][half * 2 + 0] + b0;
                float y = acc[mi][ni][half * 2 + 1] + b1;
                if (ACT == 1) {
                    x = 0.5f * x * (1.0f + erff(x * 0.70710678118654752f));
                    y = 0.5f * y * (1.0f + erff(y * 0.70710678118654752f));
                }
                float2 o; o.x = x; o.y = y;
                *(float2*)(C + (size_t)(row + half * 8) * N + col) = o;
            }
        }
    }
}

// ---------------- 3D RoPE on q,k in-place ([M, D] layout) ------------------
__global__ void rope_kernel(float* __restrict__ q, float* __restrict__ k,
                            const float* __restrict__ coords)
{
    int idx = blockIdx.x * blockDim.x + threadIdx.x;
    const int total = MM * NH * 16 * 3;
    if (idx >= total) return;
    int axis = idx % 3;
    int j    = (idx / 3) % 16;
    int h    = (idx / 48) % NH;
    int m    = idx / (48 * NH);

    float theta = powf(10000.0f, -(float)j / 16.0f);
    float ang = coords[(size_t)m * 3 + axis] * theta;
    float c = cosf(ang), sn = sinf(ang);

    size_t base = (size_t)m * DM + h * DH + j * 6 + axis * 2;
    float q0 = q[base], q1 = q[base + 1];
    q[base]     = q0 * c - q1 * sn;
    q[base + 1] = q0 * sn + q1 * c;
    float k0 = k[base], k1 = k[base + 1];
    k[base]     = k0 * c - k1 * sn;
    k[base + 1] = k0 * sn + k1 * c;
}

// ============ HMMA flash attention =========================================
// 256 threads = 8 warps (4m x 2n). TQ=128 q rows, TK=64 keys per tile.
// QK: hi/lo bf16 split (fp32-like scores). PV: single bf16 (P in [0,1]).
#define ATQ 128
#define ATK 64
#define QST 104   /* Q/K smem stride (elems): 208B = 13x16B, odd -> conflict-free */
#define PST 72    /* P / Vt stride: 144B = 9x16B, odd -> conflict-free */
#define SST 66    /* score stride (fp32) */

#define AT_QHI 0
#define AT_QLO 26624
#define AT_KHI 53248
#define AT_KLO 66560
#define AT_VT  79872
#define AT_PS  93696
#define AT_SC  112128
#define AT_MI  145920
#define AT_LI  146432
#define AT_FAC 146944
#define ATTN_SMEM 147456

__global__ void __launch_bounds__(256) attn_tc(
    const float* __restrict__ q, const float* __restrict__ k,
    const float* __restrict__ v, float* __restrict__ ctx)
{
    extern __shared__ char smc[];
    uint16_t* Qhi = (uint16_t*)(smc + AT_QHI);
    uint16_t* Qlo = (uint16_t*)(smc + AT_QLO);
    uint16_t* Khi = (uint16_t*)(smc + AT_KHI);
    uint16_t* Klo = (uint16_t*)(smc + AT_KLO);
    uint16_t* Vt  = (uint16_t*)(smc + AT_VT);
    uint16_t* Ps  = (uint16_t*)(smc + AT_PS);
    float*    Sc  = (float*)(smc + AT_SC);
    float*    mi  = (float*)(smc + AT_MI);
    float*    li  = (float*)(smc + AT_LI);
    float*    fac = (float*)(smc + AT_FAC);

    const int tid  = threadIdx.x;
    const int warp = tid >> 5;
    const int lane = tid & 31;
    const int wm   = warp & 3;    // m quadrant (32 rows)
    const int wn   = warp >> 2;   // n half

    const int q0 = blockIdx.x * ATQ;
    const int h  = blockIdx.y;
    const int b  = blockIdx.z;

    const uint32_t qhi_b = smem_u32(Qhi), qlo_b = smem_u32(Qlo);
    const uint32_t khi_b = smem_u32(Khi), klo_b = smem_u32(Klo);
    const uint32_t vt_b  = smem_u32(Vt),  ps_b  = smem_u32(Ps);

    // ldmatrix lane addressing
    const int a_row  = wm * 32 + (lane & 15);
    const int a_coff = (lane >> 4) * 8;
    const int b_row8 = (lane & 7) + ((lane >> 4) << 3);
    const int b_coff = ((lane >> 3) & 1) * 8;

    // load Q tile once (hi/lo bf16)
    for (int i = tid; i < ATQ * 24; i += 256) {
        int r = i / 24, c4 = i % 24;
        float4 a = *(const float4*)(q + (size_t)(b * SS + q0 + r) * DM + h * DH + c4 * 4);
        cvt_store(Qhi, Qlo, r * QST + c4 * 4, a);
    }
    if (tid < ATQ) { mi[tid] = -1e30f; li[tid] = 0.f; }

    const float scale = 0.10206207261596575f;   // 1/sqrt(96)
    float acco[2][6][4];
    #pragma unroll
    for (int mf = 0; mf < 2; mf++)
        #pragma unroll
        for (int nf = 0; nf < 6; nf++)
            #pragma unroll
            for (int r = 0; r < 4; r++) acco[mf][nf][r] = 0.f;

    for (int kt = 0; kt < SS / ATK; kt++) {
        const int k0 = kt * ATK;
        // K tile hi/lo
        for (int i = tid; i < ATK * 24; i += 256) {
            int r = i / 24, c4 = i % 24;
            float4 a = *(const float4*)(k + (size_t)(b * SS + k0 + r) * DM + h * DH + c4 * 4);
            cvt_store(Khi, Klo, r * QST + c4 * 4, a);
        }
        // V tile transposed, single bf16
        for (int i = tid; i < ATK * 24; i += 256) {
            int r = i / 24, c4 = i % 24;
            float4 a = *(const float4*)(v + (size_t)(b * SS + k0 + r) * DM + h * DH + c4 * 4);
            int d = c4 * 4;
            Vt[(d + 0) * PST + r] = __bfloat16_as_ushort(__float2bfloat16_rn(a.x));
            Vt[(d + 1) * PST + r] = __bfloat16_as_ushort(__float2bfloat16_rn(a.y));
            Vt[(d + 2) * PST + r] = __bfloat16_as_ushort(__float2bfloat16_rn(a.z));
            Vt[(d + 3) * PST + r] = __bfloat16_as_ushort(__float2bfloat16_rn(a.w));
        }
        __syncthreads();

        // ---- scores = Q K^T (hi/lo split) ----
        float accs[2][4][4];
        #pragma unroll
        for (int mf = 0; mf < 2; mf++)
            #pragma unroll
            for (int nf = 0; nf < 4; nf++)
                #pragma unroll
                for (int r = 0; r < 4; r++) accs[mf][nf][r] = 0.f;

        #pragma unroll
        for (int ks = 0; ks < 6; ks++) {
            const int k16 = ks * 16;
            uint32_t bh[4][2], bl[4][2];
            #pragma unroll
            for (int p = 0; p < 2; p++) {
                uint32_t off = (uint32_t)((wn * 32 + p * 16 + b_row8) * QST + b_coff + k16) * 2;
                LDSM4(bh[p*2][0], bh[p*2][1], bh[p*2+1][0], bh[p*2+1][1], khi_b + off);
                LDSM4(bl[p*2][0], bl[p*2][1], bl[p*2+1][0], bl[p*2+1][1], klo_b + off);
            }
            uint32_t a[2][4];
            #pragma unroll
            for (int mf = 0; mf < 2; mf++) {
                uint32_t off = (uint32_t)((a_row + mf * 16) * QST + a_coff + k16) * 2;
                LDSM4(a[mf][0], a[mf][1], a[mf][2], a[mf][3], qhi_b + off);
            }
            #pragma unroll
            for (int mf = 0; mf < 2; mf++)
                #pragma unroll
                for (int nf = 0; nf < 4; nf++) {
                    MMA16816(accs[mf][nf], a[mf], bh[nf]);
                    MMA16816(accs[mf][nf], a[mf], bl[nf]);
                }
            #pragma unroll
            for (int mf = 0; mf < 2; mf++) {
                uint32_t off = (uint32_t)((a_row + mf * 16) * QST + a_coff + k16) * 2;
                LDSM4(a[mf][0], a[mf][1], a[mf][2], a[mf][3], qlo_b + off);
            }
            #pragma unroll
            for (int mf = 0; mf < 2; mf++)
                #pragma unroll
                for (int nf = 0; nf < 4; nf++)
                    MMA16816(accs[mf][nf], a[mf], bh[nf]);
        }

        // store scaled scores to smem
        {
            const int er = lane >> 2, ec = (lane & 3) * 2;
            #pragma unroll
            for (int mf = 0; mf < 2; mf++)
                #pragma unroll
                for (int nf = 0; nf < 4; nf++) {
                    int row = wm * 32 + mf * 16 + er;
                    int col = wn * 32 + nf * 8 + ec;
                    float2 o0; o0.x = accs[mf][nf][0] * scale; o0.y = accs[mf][nf][1] * scale;
                    float2 o1; o1.x = accs[mf][nf][2] * scale; o1.y = accs[mf][nf][3] * scale;
                    *(float2*)(&Sc[row * SST + col]) = o0;
                    *(float2*)(&Sc[(row + 8) * SST + col]) = o1;
                }
        }
        __syncthreads();

        // ---- online softmax (2 threads per row, interleaved cols) ----
        {
            const int r = tid >> 1, h2 = tid & 1;
            const float* Srow = Sc + r * SST;
            float mx = -1e30f;
            #pragma unroll 8
            for (int j = 0; j < 32; j++) mx = fmaxf(mx, Srow[2 * j + h2]);
            mx = fmaxf(mx, __shfl_xor_sync(0xffffffffu, mx, 1));
            float m_old = mi[r];
            float m_new = fmaxf(m_old, mx);
            float sum = 0.f;
            #pragma unroll 8
            for (int j = 0; j < 32; j++) {
                float p = __expf(Srow[2 * j + h2] - m_new);
                sum += p;
                Ps[r * PST + 2 * j + h2] = __bfloat16_as_ushort(__float2bfloat16_rn(p));
            }
            sum += __shfl_xor_sync(0xffffffffu, sum, 1);
            if (h2 == 0) {
                float f = __expf(m_old - m_new);
                mi[r] = m_new;
                li[r] = li[r] * f + sum;
                fac[r] = f;
            }
        }
        __syncthreads();

        // ---- rescale accumulators, then acc += P V ----
        {
            const int er = lane >> 2;
            #pragma unroll
            for (int mf = 0; mf < 2; mf++) {
                int row = wm * 32 + mf * 16 + er;
                float f0 = fac[row], f1 = fac[row + 8];
                #pragma unroll
                for (int nf = 0; nf < 6; nf++) {
                    acco[mf][nf][0] *= f0; acco[mf][nf][1] *= f0;
                    acco[mf][nf][2] *= f1; acco[mf][nf][3] *= f1;
                }
            }
        }
        #pragma unroll
        for (int ks = 0; ks < 4; ks++) {
            const int k16 = ks * 16;
            uint32_t ap[2][4];
            #pragma unroll
            for (int mf = 0; mf < 2; mf++) {
                uint32_t off = (uint32_t)((a_row + mf * 16) * PST + a_coff + k16) * 2;
                LDSM4(ap[mf][0], ap[mf][1], ap[mf][2], ap[mf][3], ps_b + off);
            }
            uint32_t bv_[6][2];
            #pragma unroll
            for (int p = 0; p < 3; p++) {
                uint32_t off = (uint32_t)((wn * 48 + p * 16 + b_row8) * PST + b_coff + k16) * 2;
                LDSM4(bv_[p*2][0], bv_[p*2][1], bv_[p*2+1][0], bv_[p*2+1][1], vt_b + off);
            }
            #pragma unroll
            for (int mf = 0; mf < 2; mf++)
                #pragma unroll
                for (int nf = 0; nf < 6; nf++)
                    MMA16816(acco[mf][nf], ap[mf], bv_[nf]);
        }
        __syncthreads();
    }

    // epilogue: normalize and write ctx
    {
        const int er = lane >> 2, ec = (lane & 3) * 2;
        #pragma unroll
        for (int mf = 0; mf < 2; mf++) {
            int row = wm * 32 + mf * 16 + er;
            float i0 = 1.0f / li[row];
            float i1 = 1.0f / li[row + 8];
            size_t m = (size_t)(b * SS + q0 + row);
            #pragma unroll
            for (int nf = 0; nf < 6; nf++) {
                int col = h * DH + wn * 48 + nf * 8 + ec;
                float2 o0; o0.x = acco[mf][nf][0] * i0; o0.y = acco[mf][nf][1] * i0;
                float2 o1; o1.x = acco[mf][nf][2] * i1; o1.y = acco[mf][nf][3] * i1;
                *(float2*)(ctx + m * DM + col) = o0;
                *(float2*)(ctx + (m + 8) * DM + col) = o1;
            }
        }
    }
}

// ---------------- residual add + LayerNorm (one block per row) -------------
__device__ __forceinline__ float block_sum256(float val, float* red) {
    #pragma unroll
    for (int o = 16; o > 0; o >>= 1)
        val += __shfl_xor_sync(0xffffffffu, val, o);
    int w = threadIdx.x >> 5;
    if ((threadIdx.x & 31) == 0) red[w] = val;
    __syncthreads();
    if (threadIdx.x < 32) {
        float vv = (threadIdx.x < 8) ? red[threadIdx.x] : 0.f;
        #pragma unroll
        for (int o = 4; o > 0; o >>= 1)
            vv += __shfl_xor_sync(0xffffffffu, vv, o);
        if (threadIdx.x == 0) red[0] = vv;
    }
    __syncthreads();
    float r = red[0];
    __syncthreads();
    return r;
}

__global__ void __launch_bounds__(256) add_ln_kernel(
    const float* __restrict__ x, const float* __restrict__ y,
    const float* __restrict__ g, const float* __restrict__ be,
    float* __restrict__ out)
{
    __shared__ float red[32];
    size_t m = blockIdx.x;
    const float* xr = x + m * DM;
    const float* yr = y + m * DM;

    float v[3];
    float s = 0.f;
    #pragma unroll
    for (int i = 0; i < 3; i++) {
        int d = threadIdx.x + i * 256;
        v[i] = xr[d] + yr[d];
        s += v[i];
    }
    float mean = block_sum256(s, red) * (1.0f / DM);
    float sq = 0.f;
    #pragma unroll
    for (int i = 0; i < 3; i++) {
        float dd = v[i] - mean;
        sq += dd * dd;
    }
    float var = block_sum256(sq, red) * (1.0f / DM);
    float inv = rsqrtf(var + 1e-5f);
    #pragma unroll
    for (int i = 0; i < 3; i++) {
        int d = threadIdx.x + i * 256;
        out[m * DM + d] = (v[i] - mean) * inv * g[d] + be[d];
    }
}

// ---------------- launch ---------------------------------------------------
extern "C" void kernel_launch(void* const* d_in, const int* in_sizes, int n_in,
                              void* d_out, int out_size)
{
    const float* src    = (const float*)d_in[0];
    const float* coords = (const float*)d_in[1];
    const float* Wq = (const float*)d_in[2];
    const float* bq = (const float*)d_in[3];
    const float* Wk = (const float*)d_in[4];
    const float* bk = (const float*)d_in[5];
    const float* Wv = (const float*)d_in[6];
    const float* bv = (const float*)d_in[7];
    const float* Wo = (const float*)d_in[8];
    const float* bo = (const float*)d_in[9];
    const float* W1 = (const float*)d_in[10];
    const float* b1 = (const float*)d_in[11];
    const float* W2 = (const float*)d_in[12];
    const float* b2 = (const float*)d_in[13];
    const float* g1  = (const float*)d_in[14];
    const float* be1 = (const float*)d_in[15];
    const float* g2  = (const float*)d_in[16];
    const float* be2 = (const float*)d_in[17];
    float* out = (float*)d_out;

    float *q, *k, *v, *ctx, *t1, *src2, *ffh;
    cudaGetSymbolAddress((void**)&q,    g_q);
    cudaGetSymbolAddress((void**)&k,    g_k);
    cudaGetSymbolAddress((void**)&v,    g_v);
    cudaGetSymbolAddress((void**)&ctx,  g_ctx);
    cudaGetSymbolAddress((void**)&t1,   g_t1);
    cudaGetSymbolAddress((void**)&src2, g_src2);
    cudaGetSymbolAddress((void**)&ffh,  g_ffh);

    dim3 g768(DM / 128, MM / 128);     // (6, 64)
    dim3 gff(DFF / 128, MM / 128);     // (24, 64)

    // QKV projections (HMMA bf16 hi/lo split)
    gemm_tc<0><<<g768, 256>>>(src, Wq, bq, q, MM, DM, DM);
    gemm_tc<0><<<g768, 256>>>(src, Wk, bk, k, MM, DM, DM);
    gemm_tc<0><<<g768, 256>>>(src, Wv, bv, v, MM, DM, DM);

    // RoPE on q, k
    {
        int total = MM * NH * 16 * 3;
        rope_kernel<<<(total + 255) / 256, 256>>>(q, k, coords);
    }

    // attention (HMMA)
    cudaFuncSetAttribute((const void*)attn_tc,
                         cudaFuncAttributeMaxDynamicSharedMemorySize, ATTN_SMEM);
    attn_tc<<<dim3(SS / ATQ, NH, BB), 256, ATTN_SMEM>>>(q, k, v, ctx);

    // output projection + residual + LN1
    gemm_tc<0><<<g768, 256>>>(ctx, Wo, bo, t1, MM, DM, DM);
    add_ln_kernel<<<MM, 256>>>(src, t1, g1, be1, src2);

    // FFN
    gemm_tc<1><<<gff, 256>>>(src2, W1, b1, ffh, MM, DFF, DM);
    gemm_tc<0><<<g768, 256>>>(ffh, W2, b2, t1, MM, DM, DFF);
    add_ln_kernel<<<MM, 256>>>(src2, t1, g2, be2, out);
}

// round 14
// speedup vs baseline: 2.8777x; 1.5575x over previous
#include <cuda_runtime.h>
#include <cuda_bf16.h>
#include <math.h>
#include <stddef.h>
#include <stdint.h>

#define BB 4
#define SS 2048
#define DM 768
#define NH 8
#define DH 96
#define DFF 3072
#define MM (BB*SS)   /* 8192 rows */

// ---------------- scratch (device globals: allocation-free) ----------------
__device__ float g_q[MM*DM];
__device__ float g_k[MM*DM];
__device__ float g_v[MM*DM];
__device__ float g_ctx[MM*DM];
__device__ float g_t1[MM*DM];
__device__ float g_src2[MM*DM];
__device__ float g_ffh[(size_t)MM*DFF];

// ================= helpers =================================================
static __device__ __forceinline__ uint32_t smem_u32(const void* p) {
    uint32_t a;
    asm("{ .reg .u64 t; cvta.to.shared.u64 t, %1; cvt.u32.u64 %0, t; }"
        : "=r"(a) : "l"(p));
    return a;
}

#define LDSM4(R0,R1,R2,R3,addr) \
    asm volatile("ldmatrix.sync.aligned.m8n8.x4.shared.b16 {%0,%1,%2,%3}, [%4];" \
        : "=r"(R0),"=r"(R1),"=r"(R2),"=r"(R3) : "r"(addr))

#define LDSM4T(R0,R1,R2,R3,addr) \
    asm volatile("ldmatrix.sync.aligned.m8n8.x4.trans.shared.b16 {%0,%1,%2,%3}, [%4];" \
        : "=r"(R0),"=r"(R1),"=r"(R2),"=r"(R3) : "r"(addr))

#define MMA16816(d, a, b) \
    asm volatile("mma.sync.aligned.m16n8k16.row.col.f32.bf16.bf16.f32 " \
        "{%0,%1,%2,%3}, {%4,%5,%6,%7}, {%8,%9}, {%0,%1,%2,%3};" \
        : "+f"((d)[0]), "+f"((d)[1]), "+f"((d)[2]), "+f"((d)[3]) \
        : "r"((a)[0]), "r"((a)[1]), "r"((a)[2]), "r"((a)[3]), \
          "r"((b)[0]), "r"((b)[1]))

// convert one float4 to hi/lo bf16x2 pairs and store 8B each
static __device__ __forceinline__ void cvt_store(
    uint16_t* __restrict__ hi, uint16_t* __restrict__ lo, int eoff, float4 a)
{
    __nv_bfloat16 hx = __float2bfloat16_rn(a.x);
    __nv_bfloat16 hy = __float2bfloat16_rn(a.y);
    __nv_bfloat16 hz = __float2bfloat16_rn(a.z);
    __nv_bfloat16 hw = __float2bfloat16_rn(a.w);
    __nv_bfloat162 h0; h0.x = hx; h0.y = hy;
    __nv_bfloat162 h1; h1.x = hz; h1.y = hw;
    __nv_bfloat162 l0 = __floats2bfloat162_rn(a.x - __bfloat162float(hx),
                                              a.y - __bfloat162float(hy));
    __nv_bfloat162 l1 = __floats2bfloat162_rn(a.z - __bfloat162float(hz),
                                              a.w - __bfloat162float(hw));
    uint2 hv; hv.x = *(uint32_t*)&h0; hv.y = *(uint32_t*)&h1;
    uint2 lv; lv.x = *(uint32_t*)&l0; lv.y = *(uint32_t*)&l1;
    *(uint2*)(hi + eoff) = hv;
    *(uint2*)(lo + eoff) = lv;
}

// pack float4 -> 4 bf16 (8B)
static __device__ __forceinline__ void cvt_store1(
    uint16_t* __restrict__ dst, int eoff, float4 a)
{
    __nv_bfloat162 p0 = __floats2bfloat162_rn(a.x, a.y);
    __nv_bfloat162 p1 = __floats2bfloat162_rn(a.z, a.w);
    uint2 pv; pv.x = *(uint32_t*)&p0; pv.y = *(uint32_t*)&p1;
    *(uint2*)(dst + eoff) = pv;
}

// ============ HMMA GEMM: C[M,N] = A[M,K] @ B[N,K]^T + bias (opt GELU) ======
// pipelined: next tile's gmem loads issue before current tile's MMA phase.
#define KS 40

template<int ACT>
__global__ void __launch_bounds__(256) gemm_tc(
    const float* __restrict__ A, const float* __restrict__ B,
    const float* __restrict__ bias, float* __restrict__ C,
    int M, int N, int K)
{
    __shared__ __align__(16) uint16_t As_hi[128*KS];
    __shared__ __align__(16) uint16_t As_lo[128*KS];
    __shared__ __align__(16) uint16_t Bs_hi[128*KS];
    __shared__ __align__(16) uint16_t Bs_lo[128*KS];

    const int tid  = threadIdx.x;
    const int warp = tid >> 5;
    const int lane = tid & 31;
    const int wm   = warp & 1;
    const int wn   = warp >> 1;

    const int m0 = blockIdx.y * 128;
    const int n0 = blockIdx.x * 128;
    const float* Ab = A + (size_t)m0 * K;
    const float* Bb = B + (size_t)n0 * K;

    const int l_row = tid >> 3;
    const int l_c4  = tid & 7;

    const uint32_t a_hi_base = smem_u32(As_hi);
    const uint32_t a_lo_base = smem_u32(As_lo);
    const uint32_t b_hi_base = smem_u32(Bs_hi);
    const uint32_t b_lo_base = smem_u32(Bs_lo);
    const int a_row  = wm * 64 + (lane & 15);
    const int a_coff = (lane >> 4) * 8;
    const int b_row  = wn * 32 + (lane & 7) + ((lane >> 4) << 3);
    const int b_coff = ((lane >> 3) & 1) * 8;

    float acc[4][4][4];
    #pragma unroll
    for (int mi = 0; mi < 4; mi++)
        #pragma unroll
        for (int ni = 0; ni < 4; ni++)
            #pragma unroll
            for (int r = 0; r < 4; r++) acc[mi][ni][r] = 0.f;

    float4 av[4], bv[4];
    // preload tile 0
    #pragma unroll
    for (int i = 0; i < 4; i++) {
        av[i] = *(const float4*)(Ab + (size_t)(l_row + i * 32) * K + l_c4 * 4);
        bv[i] = *(const float4*)(Bb + (size_t)(l_row + i * 32) * K + l_c4 * 4);
    }

    const int T = K >> 5;
    for (int t = 0; t < T; t++) {
        __syncthreads();   // prior tile's ldmatrix reads complete
        #pragma unroll
        for (int i = 0; i < 4; i++) {
            int eoff = (l_row + i * 32) * KS + l_c4 * 4;
            cvt_store(As_hi, As_lo, eoff, av[i]);
            cvt_store(Bs_hi, Bs_lo, eoff, bv[i]);
        }
        __syncthreads();

        // issue next tile's loads; latency hides behind MMA phase
        if (t + 1 < T) {
            const int kn = (t + 1) << 5;
            #pragma unroll
            for (int i = 0; i < 4; i++) {
                av[i] = *(const float4*)(Ab + (size_t)(l_row + i * 32) * K + kn + l_c4 * 4);
                bv[i] = *(const float4*)(Bb + (size_t)(l_row + i * 32) * K + kn + l_c4 * 4);
            }
        }

        #pragma unroll
        for (int kh = 0; kh < 2; kh++) {
            const int k16 = kh * 16;
            uint32_t bh[4][2], bl[4][2];
            #pragma unroll
            for (int p = 0; p < 2; p++) {
                uint32_t off = (uint32_t)((b_row + p * 16) * KS + b_coff + k16) * 2;
                LDSM4(bh[p*2][0], bh[p*2][1], bh[p*2+1][0], bh[p*2+1][1], b_hi_base + off);
                LDSM4(bl[p*2][0], bl[p*2][1], bl[p*2+1][0], bl[p*2+1][1], b_lo_base + off);
            }
            uint32_t a[4][4];
            #pragma unroll
            for (int mi = 0; mi < 4; mi++) {
                uint32_t off = (uint32_t)((a_row + mi * 16) * KS + a_coff + k16) * 2;
                LDSM4(a[mi][0], a[mi][1], a[mi][2], a[mi][3], a_hi_base + off);
            }
            #pragma unroll
            for (int mi = 0; mi < 4; mi++)
                #pragma unroll
                for (int ni = 0; ni < 4; ni++) {
                    MMA16816(acc[mi][ni], a[mi], bh[ni]);
                    MMA16816(acc[mi][ni], a[mi], bl[ni]);
                }
            #pragma unroll
            for (int mi = 0; mi < 4; mi++) {
                uint32_t off = (uint32_t)((a_row + mi * 16) * KS + a_coff + k16) * 2;
                LDSM4(a[mi][0], a[mi][1], a[mi][2], a[mi][3], a_lo_base + off);
            }
            #pragma unroll
            for (int mi = 0; mi < 4; mi++)
                #pragma unroll
                for (int ni = 0; ni < 4; ni++)
                    MMA16816(acc[mi][ni], a[mi], bh[ni]);
        }
    }

    const int er = lane >> 2;
    const int ec = (lane & 3) * 2;
    #pragma unroll
    for (int mi = 0; mi < 4; mi++) {
        #pragma unroll
        for (int ni = 0; ni < 4; ni++) {
            int row = m0 + wm * 64 + mi * 16 + er;
            int col = n0 + wn * 32 + ni * 8 + ec;
            float b0 = bias[col], b1 = bias[col + 1];
            #pragma unroll
            for (int half = 0; half < 2; half++) {
                float x = acc[mi][ni][half * 2 + 0] + b0;
                float y = acc[mi][ni][half * 2 + 1] + b1;
                if (ACT == 1) {
                    x = 0.5f * x * (1.0f + erff(x * 0.70710678118654752f));
                    y = 0.5f * y * (1.0f + erff(y * 0.70710678118654752f));
                }
                float2 o; o.x = x; o.y = y;
                *(float2*)(C + (size_t)(row + half * 8) * N + col) = o;
            }
        }
    }
}

// ---------------- 3D RoPE on q,k in-place ([M, D] layout) ------------------
__global__ void rope_kernel(float* __restrict__ q, float* __restrict__ k,
                            const float* __restrict__ coords)
{
    int idx = blockIdx.x * blockDim.x + threadIdx.x;
    const int total = MM * NH * 16 * 3;
    if (idx >= total) return;
    int axis = idx % 3;
    int j    = (idx / 3) % 16;
    int h    = (idx / 48) % NH;
    int m    = idx / (48 * NH);

    float theta = powf(10000.0f, -(float)j / 16.0f);
    float ang = coords[(size_t)m * 3 + axis] * theta;
    float c = cosf(ang), sn = sinf(ang);

    size_t base = (size_t)m * DM + h * DH + j * 6 + axis * 2;
    float q0 = q[base], q1 = q[base + 1];
    q[base]     = q0 * c - q1 * sn;
    q[base + 1] = q0 * sn + q1 * c;
    float k0 = k[base], k1 = k[base + 1];
    k[base]     = k0 * c - k1 * sn;
    k[base + 1] = k0 * sn + k1 * c;
}

// ============ HMMA flash attention =========================================
// 256 threads = 8 warps (4m x 2n). TQ=128 q rows, TK=64 keys per tile.
// QK: hi/lo bf16 split. PV: single bf16, V row-major + ldmatrix.trans.
// Pipelined: next K/V tile gmem loads issue before QK/softmax/PV of current.
#define ATQ 128
#define ATK 64
#define QST 104   /* Q/K/V smem stride (elems): 208B = 13x16B odd -> conflict-free */
#define PST 72    /* P stride: 144B = 9x16B odd -> conflict-free */
#define SST 66    /* score stride (fp32) */

#define AT_QHI 0
#define AT_QLO 26624
#define AT_KHI 53248
#define AT_KLO 66560
#define AT_VR  79872
#define AT_PS  93184
#define AT_SC  111616
#define AT_MI  145408
#define AT_LI  145920
#define AT_FAC 146432
#define ATTN_SMEM 146944

__global__ void __launch_bounds__(256) attn_tc(
    const float* __restrict__ q, const float* __restrict__ k,
    const float* __restrict__ v, float* __restrict__ ctx)
{
    extern __shared__ char smc[];
    uint16_t* Qhi = (uint16_t*)(smc + AT_QHI);
    uint16_t* Qlo = (uint16_t*)(smc + AT_QLO);
    uint16_t* Khi = (uint16_t*)(smc + AT_KHI);
    uint16_t* Klo = (uint16_t*)(smc + AT_KLO);
    uint16_t* Vr  = (uint16_t*)(smc + AT_VR);
    uint16_t* Ps  = (uint16_t*)(smc + AT_PS);
    float*    Sc  = (float*)(smc + AT_SC);
    float*    mi  = (float*)(smc + AT_MI);
    float*    li  = (float*)(smc + AT_LI);
    float*    fac = (float*)(smc + AT_FAC);

    const int tid  = threadIdx.x;
    const int warp = tid >> 5;
    const int lane = tid & 31;
    const int wm   = warp & 3;    // m quadrant (32 rows)
    const int wn   = warp >> 2;   // n half

    const int q0 = blockIdx.x * ATQ;
    const int h  = blockIdx.y;
    const int b  = blockIdx.z;

    const uint32_t qhi_b = smem_u32(Qhi), qlo_b = smem_u32(Qlo);
    const uint32_t khi_b = smem_u32(Khi), klo_b = smem_u32(Klo);
    const uint32_t vr_b  = smem_u32(Vr),  ps_b  = smem_u32(Ps);

    // ldmatrix lane addressing
    const int a_row  = wm * 32 + (lane & 15);
    const int a_coff = (lane >> 4) * 8;
    const int b_row8 = (lane & 7) + ((lane >> 4) << 3);
    const int b_coff = ((lane >> 3) & 1) * 8;
    // trans-load addressing for V (B operand of PV)
    const int vt_krow = ((lane >> 3) & 1) * 8 + (lane & 7);
    const int vt_c8   = (lane >> 4) * 8;

    // load Q tile once (hi/lo bf16)
    for (int i = tid; i < ATQ * 24; i += 256) {
        int r = i / 24, c4 = i % 24;
        float4 a = *(const float4*)(q + (size_t)(b * SS + q0 + r) * DM + h * DH + c4 * 4);
        cvt_store(Qhi, Qlo, r * QST + c4 * 4, a);
    }
    if (tid < ATQ) { mi[tid] = -1e30f; li[tid] = 0.f; }

    const float scale = 0.10206207261596575f;   // 1/sqrt(96)
    float acco[2][6][4];
    #pragma unroll
    for (int mf = 0; mf < 2; mf++)
        #pragma unroll
        for (int nf = 0; nf < 6; nf++)
            #pragma unroll
            for (int r = 0; r < 4; r++) acco[mf][nf][r] = 0.f;

    // prefetch K/V tile 0 into registers
    float4 kreg[6], vreg[6];
    {
        #pragma unroll
        for (int j = 0; j < 6; j++) {
            int i = j * 256 + tid;
            int r = i / 24, c4 = i % 24;
            kreg[j] = *(const float4*)(k + (size_t)(b * SS + r) * DM + h * DH + c4 * 4);
            vreg[j] = *(const float4*)(v + (size_t)(b * SS + r) * DM + h * DH + c4 * 4);
        }
    }

    for (int kt = 0; kt < SS / ATK; kt++) {
        __syncthreads();   // prior tile's smem reads done; Q visible on kt=0
        #pragma unroll
        for (int j = 0; j < 6; j++) {
            int i = j * 256 + tid;
            int r = i / 24, c4 = i % 24;
            cvt_store(Khi, Klo, r * QST + c4 * 4, kreg[j]);
            cvt_store1(Vr, r * QST + c4 * 4, vreg[j]);
        }
        __syncthreads();

        // issue next tile's gmem loads (latency hides behind QK/softmax/PV)
        if (kt + 1 < SS / ATK) {
            const int kn = (kt + 1) * ATK;
            #pragma unroll
            for (int j = 0; j < 6; j++) {
                int i = j * 256 + tid;
                int r = i / 24, c4 = i % 24;
                kreg[j] = *(const float4*)(k + (size_t)(b * SS + kn + r) * DM + h * DH + c4 * 4);
                vreg[j] = *(const float4*)(v + (size_t)(b * SS + kn + r) * DM + h * DH + c4 * 4);
            }
        }

        // ---- scores = Q K^T (hi/lo split) ----
        float accs[2][4][4];
        #pragma unroll
        for (int mf = 0; mf < 2; mf++)
            #pragma unroll
            for (int nf = 0; nf < 4; nf++)
                #pragma unroll
                for (int r = 0; r < 4; r++) accs[mf][nf][r] = 0.f;

        #pragma unroll
        for (int ks = 0; ks < 6; ks++) {
            const int k16 = ks * 16;
            uint32_t bh[4][2], bl[4][2];
            #pragma unroll
            for (int p = 0; p < 2; p++) {
                uint32_t off = (uint32_t)((wn * 32 + p * 16 + b_row8) * QST + b_coff + k16) * 2;
                LDSM4(bh[p*2][0], bh[p*2][1], bh[p*2+1][0], bh[p*2+1][1], khi_b + off);
                LDSM4(bl[p*2][0], bl[p*2][1], bl[p*2+1][0], bl[p*2+1][1], klo_b + off);
            }
            uint32_t a[2][4];
            #pragma unroll
            for (int mf = 0; mf < 2; mf++) {
                uint32_t off = (uint32_t)((a_row + mf * 16) * QST + a_coff + k16) * 2;
                LDSM4(a[mf][0], a[mf][1], a[mf][2], a[mf][3], qhi_b + off);
            }
            #pragma unroll
            for (int mf = 0; mf < 2; mf++)
                #pragma unroll
                for (int nf = 0; nf < 4; nf++) {
                    MMA16816(accs[mf][nf], a[mf], bh[nf]);
                    MMA16816(accs[mf][nf], a[mf], bl[nf]);
                }
            #pragma unroll
            for (int mf = 0; mf < 2; mf++) {
                uint32_t off = (uint32_t)((a_row + mf * 16) * QST + a_coff + k16) * 2;
                LDSM4(a[mf][0], a[mf][1], a[mf][2], a[mf][3], qlo_b + off);
            }
            #pragma unroll
            for (int mf = 0; mf < 2; mf++)
                #pragma unroll
                for (int nf = 0; nf < 4; nf++)
                    MMA16816(accs[mf][nf], a[mf], bh[nf]);
        }

        // store scaled scores to smem
        {
            const int er = lane >> 2, ec = (lane & 3) * 2;
            #pragma unroll
            for (int mf = 0; mf < 2; mf++)
                #pragma unroll
                for (int nf = 0; nf < 4; nf++) {
                    int row = wm * 32 + mf * 16 + er;
                    int col = wn * 32 + nf * 8 + ec;
                    float2 o0; o0.x = accs[mf][nf][0] * scale; o0.y = accs[mf][nf][1] * scale;
                    float2 o1; o1.x = accs[mf][nf][2] * scale; o1.y = accs[mf][nf][3] * scale;
                    *(float2*)(&Sc[row * SST + col]) = o0;
                    *(float2*)(&Sc[(row + 8) * SST + col]) = o1;
                }
        }
        __syncthreads();

        // ---- online softmax (2 threads per row, interleaved cols) ----
        {
            const int r = tid >> 1, h2 = tid & 1;
            const float* Srow = Sc + r * SST;
            float mx = -1e30f;
            #pragma unroll 8
            for (int j = 0; j < 32; j++) mx = fmaxf(mx, Srow[2 * j + h2]);
            mx = fmaxf(mx, __shfl_xor_sync(0xffffffffu, mx, 1));
            float m_old = mi[r];
            float m_new = fmaxf(m_old, mx);
            float sum = 0.f;
            #pragma unroll 8
            for (int j = 0; j < 32; j++) {
                float p = __expf(Srow[2 * j + h2] - m_new);
                sum += p;
                Ps[r * PST + 2 * j + h2] = __bfloat16_as_ushort(__float2bfloat16_rn(p));
            }
            sum += __shfl_xor_sync(0xffffffffu, sum, 1);
            if (h2 == 0) {
                float f = __expf(m_old - m_new);
                mi[r] = m_new;
                li[r] = li[r] * f + sum;
                fac[r] = f;
            }
        }
        __syncthreads();

        // ---- rescale accumulators, then acc += P V ----
        {
            const int er = lane >> 2;
            #pragma unroll
            for (int mf = 0; mf < 2; mf++) {
                int row = wm * 32 + mf * 16 + er;
                float f0 = fac[row], f1 = fac[row + 8];
                #pragma unroll
                for (int nf = 0; nf < 6; nf++) {
                    acco[mf][nf][0] *= f0; acco[mf][nf][1] *= f0;
                    acco[mf][nf][2] *= f1; acco[mf][nf][3] *= f1;
                }
            }
        }
        #pragma unroll
        for (int ks = 0; ks < 4; ks++) {
            const int k16 = ks * 16;
            uint32_t ap[2][4];
            #pragma unroll
            for (int mf = 0; mf < 2; mf++) {
                uint32_t off = (uint32_t)((a_row + mf * 16) * PST + a_coff + k16) * 2;
                LDSM4(ap[mf][0], ap[mf][1], ap[mf][2], ap[mf][3], ps_b + off);
            }
            uint32_t bv_[6][2];
            #pragma unroll
            for (int p = 0; p < 3; p++) {
                uint32_t off = (uint32_t)((k16 + vt_krow) * QST + wn * 48 + p * 16 + vt_c8) * 2;
                LDSM4T(bv_[p*2][0], bv_[p*2][1], bv_[p*2+1][0], bv_[p*2+1][1], vr_b + off);
            }
            #pragma unroll
            for (int mf = 0; mf < 2; mf++)
                #pragma unroll
                for (int nf = 0; nf < 6; nf++)
                    MMA16816(acco[mf][nf], ap[mf], bv_[nf]);
        }
    }

    // epilogue: normalize and write ctx
    {
        const int er = lane >> 2, ec = (lane & 3) * 2;
        #pragma unroll
        for (int mf = 0; mf < 2; mf++) {
            int row = wm * 32 + mf * 16 + er;
            float i0 = 1.0f / li[row];
            float i1 = 1.0f / li[row + 8];
            size_t m = (size_t)(b * SS + q0 + row);
            #pragma unroll
            for (int nf = 0; nf < 6; nf++) {
                int col = h * DH + wn * 48 + nf * 8 + ec;
                float2 o0; o0.x = acco[mf][nf][0] * i0; o0.y = acco[mf][nf][1] * i0;
                float2 o1; o1.x = acco[mf][nf][2] * i1; o1.y = acco[mf][nf][3] * i1;
                *(float2*)(ctx + m * DM + col) = o0;
                *(float2*)(ctx + (m + 8) * DM + col) = o1;
            }
        }
    }
}

// ---------------- residual add + LayerNorm (one block per row) -------------
__device__ __forceinline__ float block_sum256(float val, float* red) {
    #pragma unroll
    for (int o = 16; o > 0; o >>= 1)
        val += __shfl_xor_sync(0xffffffffu, val, o);
    int w = threadIdx.x >> 5;
    if ((threadIdx.x & 31) == 0) red[w] = val;
    __syncthreads();
    if (threadIdx.x < 32) {
        float vv = (threadIdx.x < 8) ? red[threadIdx.x] : 0.f;
        #pragma unroll
        for (int o = 4; o > 0; o >>= 1)
            vv += __shfl_xor_sync(0xffffffffu, vv, o);
        if (threadIdx.x == 0) red[0] = vv;
    }
    __syncthreads();
    float r = red[0];
    __syncthreads();
    return r;
}

__global__ void __launch_bounds__(256) add_ln_kernel(
    const float* __restrict__ x, const float* __restrict__ y,
    const float* __restrict__ g, const float* __restrict__ be,
    float* __restrict__ out)
{
    __shared__ float red[32];
    size_t m = blockIdx.x;
    const float* xr = x + m * DM;
    const float* yr = y + m * DM;

    float v[3];
    float s = 0.f;
    #pragma unroll
    for (int i = 0; i < 3; i++) {
        int d = threadIdx.x + i * 256;
        v[i] = xr[d] + yr[d];
        s += v[i];
    }
    float mean = block_sum256(s, red) * (1.0f / DM);
    float sq = 0.f;
    #pragma unroll
    for (int i = 0; i < 3; i++) {
        float dd = v[i] - mean;
        sq += dd * dd;
    }
    float var = block_sum256(sq, red) * (1.0f / DM);
    float inv = rsqrtf(var + 1e-5f);
    #pragma unroll
    for (int i = 0; i < 3; i++) {
        int d = threadIdx.x + i * 256;
        out[m * DM + d] = (v[i] - mean) * inv * g[d] + be[d];
    }
}

// ---------------- launch ---------------------------------------------------
extern "C" void kernel_launch(void* const* d_in, const int* in_sizes, int n_in,
                              void* d_out, int out_size)
{
    const float* src    = (const float*)d_in[0];
    const float* coords = (const float*)d_in[1];
    const float* Wq = (const float*)d_in[2];
    const float* bq = (const float*)d_in[3];
    const float* Wk = (const float*)d_in[4];
    const float* bk = (const float*)d_in[5];
    const float* Wv = (const float*)d_in[6];
    const float* bv = (const float*)d_in[7];
    const float* Wo = (const float*)d_in[8];
    const float* bo = (const float*)d_in[9];
    const float* W1 = (const float*)d_in[10];
    const float* b1 = (const float*)d_in[11];
    const float* W2 = (const float*)d_in[12];
    const float* b2 = (const float*)d_in[13];
    const float* g1  = (const float*)d_in[14];
    const float* be1 = (const float*)d_in[15];
    const float* g2  = (const float*)d_in[16];
    const float* be2 = (const float*)d_in[17];
    float* out = (float*)d_out;

    float *q, *k, *v, *ctx, *t1, *src2, *ffh;
    cudaGetSymbolAddress((void**)&q,    g_q);
    cudaGetSymbolAddress((void**)&k,    g_k);
    cudaGetSymbolAddress((void**)&v,    g_v);
    cudaGetSymbolAddress((void**)&ctx,  g_ctx);
    cudaGetSymbolAddress((void**)&t1,   g_t1);
    cudaGetSymbolAddress((void**)&src2, g_src2);
    cudaGetSymbolAddress((void**)&ffh,  g_ffh);

    dim3 g768(DM / 128, MM / 128);     // (6, 64)
    dim3 gff(DFF / 128, MM / 128);     // (24, 64)

    // QKV projections (HMMA bf16 hi/lo split, pipelined)
    gemm_tc<0><<<g768, 256>>>(src, Wq, bq, q, MM, DM, DM);
    gemm_tc<0><<<g768, 256>>>(src, Wk, bk, k, MM, DM, DM);
    gemm_tc<0><<<g768, 256>>>(src, Wv, bv, v, MM, DM, DM);

    // RoPE on q, k
    {
        int total = MM * NH * 16 * 3;
        rope_kernel<<<(total + 255) / 256, 256>>>(q, k, coords);
    }

    // attention (HMMA, pipelined, trans-V)
    cudaFuncSetAttribute((const void*)attn_tc,
                         cudaFuncAttributeMaxDynamicSharedMemorySize, ATTN_SMEM);
    attn_tc<<<dim3(SS / ATQ, NH, BB), 256, ATTN_SMEM>>>(q, k, v, ctx);

    // output projection + residual + LN1
    gemm_tc<0><<<g768, 256>>>(ctx, Wo, bo, t1, MM, DM, DM);
    add_ln_kernel<<<MM, 256>>>(src, t1, g1, be1, src2);

    // FFN
    gemm_tc<1><<<gff, 256>>>(src2, W1, b1, ffh, MM, DFF, DM);
    gemm_tc<0><<<g768, 256>>>(ffh, W2, b2, t1, MM, DM, DFF);
    add_ln_kernel<<<MM, 256>>>(src2, t1, g2, be2, out);
}

// round 15
// speedup vs baseline: 2.8957x; 1.0063x over previous
#include <cuda_runtime.h>
#include <cuda_bf16.h>
#include <math.h>
#include <stddef.h>
#include <stdint.h>

#define BB 4
#define SS 2048
#define DM 768
#define NH 8
#define DH 96
#define DFF 3072
#define MM (BB*SS)   /* 8192 rows */

// weight offsets in the preconverted hi/lo buffers
#define OWQ 0
#define OWK 589824
#define OWV 1179648
#define OWO 1769472
#define OW1 2359296
#define OW2 4718592
#define NWTOT 7077888

// ---------------- scratch (device globals: allocation-free) ----------------
__device__ float g_q[MM*DM];
__device__ float g_k[MM*DM];
__device__ float g_v[MM*DM];
__device__ float g_ctx[MM*DM];
__device__ float g_t1[MM*DM];
__device__ float g_src2[MM*DM];
__device__ float g_ffh[(size_t)MM*DFF];
__device__ uint16_t g_whi[NWTOT];
__device__ uint16_t g_wlo[NWTOT];

// ================= helpers =================================================
static __device__ __forceinline__ uint32_t smem_u32(const void* p) {
    uint32_t a;
    asm("{ .reg .u64 t; cvta.to.shared.u64 t, %1; cvt.u32.u64 %0, t; }"
        : "=r"(a) : "l"(p));
    return a;
}

#define LDSM4(R0,R1,R2,R3,addr) \
    asm volatile("ldmatrix.sync.aligned.m8n8.x4.shared.b16 {%0,%1,%2,%3}, [%4];" \
        : "=r"(R0),"=r"(R1),"=r"(R2),"=r"(R3) : "r"(addr))

#define LDSM4T(R0,R1,R2,R3,addr) \
    asm volatile("ldmatrix.sync.aligned.m8n8.x4.trans.shared.b16 {%0,%1,%2,%3}, [%4];" \
        : "=r"(R0),"=r"(R1),"=r"(R2),"=r"(R3) : "r"(addr))

#define MMA16816(d, a, b) \
    asm volatile("mma.sync.aligned.m16n8k16.row.col.f32.bf16.bf16.f32 " \
        "{%0,%1,%2,%3}, {%4,%5,%6,%7}, {%8,%9}, {%0,%1,%2,%3};" \
        : "+f"((d)[0]), "+f"((d)[1]), "+f"((d)[2]), "+f"((d)[3]) \
        : "r"((a)[0]), "r"((a)[1]), "r"((a)[2]), "r"((a)[3]), \
          "r"((b)[0]), "r"((b)[1]))

// convert one float4 to hi/lo bf16x2 pairs and store 8B each
static __device__ __forceinline__ void cvt_store(
    uint16_t* __restrict__ hi, uint16_t* __restrict__ lo, int eoff, float4 a)
{
    __nv_bfloat16 hx = __float2bfloat16_rn(a.x);
    __nv_bfloat16 hy = __float2bfloat16_rn(a.y);
    __nv_bfloat16 hz = __float2bfloat16_rn(a.z);
    __nv_bfloat16 hw = __float2bfloat16_rn(a.w);
    __nv_bfloat162 h0; h0.x = hx; h0.y = hy;
    __nv_bfloat162 h1; h1.x = hz; h1.y = hw;
    __nv_bfloat162 l0 = __floats2bfloat162_rn(a.x - __bfloat162float(hx),
                                              a.y - __bfloat162float(hy));
    __nv_bfloat162 l1 = __floats2bfloat162_rn(a.z - __bfloat162float(hz),
                                              a.w - __bfloat162float(hw));
    uint2 hv; hv.x = *(uint32_t*)&h0; hv.y = *(uint32_t*)&h1;
    uint2 lv; lv.x = *(uint32_t*)&l0; lv.y = *(uint32_t*)&l1;
    *(uint2*)(hi + eoff) = hv;
    *(uint2*)(lo + eoff) = lv;
}

// pack float4 -> 4 bf16 (8B)
static __device__ __forceinline__ void cvt_store1(
    uint16_t* __restrict__ dst, int eoff, float4 a)
{
    __nv_bfloat162 p0 = __floats2bfloat162_rn(a.x, a.y);
    __nv_bfloat162 p1 = __floats2bfloat162_rn(a.z, a.w);
    uint2 pv; pv.x = *(uint32_t*)&p0; pv.y = *(uint32_t*)&p1;
    *(uint2*)(dst + eoff) = pv;
}

// ---------------- weight preconversion: fp32 -> hi/lo bf16 -----------------
__global__ void cvt_w_kernel(const float* __restrict__ w,
                             uint16_t* __restrict__ hi,
                             uint16_t* __restrict__ lo, int n4)
{
    int i = blockIdx.x * blockDim.x + threadIdx.x;
    if (i >= n4) return;
    float4 a = ((const float4*)w)[i];
    cvt_store(hi, lo, i * 4, a);
}

// ============ HMMA GEMM: C[M,N] = A[M,K] @ B[N,K]^T + bias (opt GELU) ======
// pipelined; B operand preconverted to hi/lo bf16 (weights).
#define KS 40

template<int ACT>
__global__ void __launch_bounds__(256) gemm_tc(
    const float* __restrict__ A,
    const uint16_t* __restrict__ Bhi_g, const uint16_t* __restrict__ Blo_g,
    const float* __restrict__ bias, float* __restrict__ C,
    int M, int N, int K)
{
    __shared__ __align__(16) uint16_t As_hi[128*KS];
    __shared__ __align__(16) uint16_t As_lo[128*KS];
    __shared__ __align__(16) uint16_t Bs_hi[128*KS];
    __shared__ __align__(16) uint16_t Bs_lo[128*KS];

    const int tid  = threadIdx.x;
    const int warp = tid >> 5;
    const int lane = tid & 31;
    const int wm   = warp & 1;
    const int wn   = warp >> 1;

    const int m0 = blockIdx.y * 128;
    const int n0 = blockIdx.x * 128;
    const float* Ab = A + (size_t)m0 * K;
    const uint16_t* Bb_hi = Bhi_g + (size_t)n0 * K;
    const uint16_t* Bb_lo = Blo_g + (size_t)n0 * K;

    const int l_row = tid >> 3;        // A loader: 0..31 (+32 per pass)
    const int l_c4  = tid & 7;
    const int bl_row = tid >> 2;       // B loader: 0..63 (+64 second chunk)
    const int bl_c   = (tid & 3) * 8;  // 8-elem (16B) column within 32-K

    const uint32_t a_hi_base = smem_u32(As_hi);
    const uint32_t a_lo_base = smem_u32(As_lo);
    const uint32_t b_hi_base = smem_u32(Bs_hi);
    const uint32_t b_lo_base = smem_u32(Bs_lo);
    const int a_row  = wm * 64 + (lane & 15);
    const int a_coff = (lane >> 4) * 8;
    const int b_row  = wn * 32 + (lane & 7) + ((lane >> 4) << 3);
    const int b_coff = ((lane >> 3) & 1) * 8;

    float acc[4][4][4];
    #pragma unroll
    for (int mi = 0; mi < 4; mi++)
        #pragma unroll
        for (int ni = 0; ni < 4; ni++)
            #pragma unroll
            for (int r = 0; r < 4; r++) acc[mi][ni][r] = 0.f;

    float4 av[4];
    uint4 ph[2], pl[2];
    // preload tile 0
    #pragma unroll
    for (int i = 0; i < 4; i++)
        av[i] = *(const float4*)(Ab + (size_t)(l_row + i * 32) * K + l_c4 * 4);
    #pragma unroll
    for (int j = 0; j < 2; j++) {
        ph[j] = *(const uint4*)(Bb_hi + (size_t)(bl_row + j * 64) * K + bl_c);
        pl[j] = *(const uint4*)(Bb_lo + (size_t)(bl_row + j * 64) * K + bl_c);
    }

    const int T = K >> 5;
    for (int t = 0; t < T; t++) {
        __syncthreads();   // prior tile's ldmatrix reads complete
        #pragma unroll
        for (int i = 0; i < 4; i++) {
            int eoff = (l_row + i * 32) * KS + l_c4 * 4;
            cvt_store(As_hi, As_lo, eoff, av[i]);
        }
        #pragma unroll
        for (int j = 0; j < 2; j++) {
            uint32_t boff = (uint32_t)((bl_row + j * 64) * KS + bl_c) * 2;
            *(uint4*)((char*)Bs_hi + boff) = ph[j];
            *(uint4*)((char*)Bs_lo + boff) = pl[j];
        }
        __syncthreads();

        // issue next tile's loads; latency hides behind MMA phase
        if (t + 1 < T) {
            const int kn = (t + 1) << 5;
            #pragma unroll
            for (int i = 0; i < 4; i++)
                av[i] = *(const float4*)(Ab + (size_t)(l_row + i * 32) * K + kn + l_c4 * 4);
            #pragma unroll
            for (int j = 0; j < 2; j++) {
                ph[j] = *(const uint4*)(Bb_hi + (size_t)(bl_row + j * 64) * K + kn + bl_c);
                pl[j] = *(const uint4*)(Bb_lo + (size_t)(bl_row + j * 64) * K + kn + bl_c);
            }
        }

        #pragma unroll
        for (int kh = 0; kh < 2; kh++) {
            const int k16 = kh * 16;
            uint32_t bh[4][2], bl_[4][2];
            #pragma unroll
            for (int p = 0; p < 2; p++) {
                uint32_t off = (uint32_t)((b_row + p * 16) * KS + b_coff + k16) * 2;
                LDSM4(bh[p*2][0], bh[p*2][1], bh[p*2+1][0], bh[p*2+1][1], b_hi_base + off);
                LDSM4(bl_[p*2][0], bl_[p*2][1], bl_[p*2+1][0], bl_[p*2+1][1], b_lo_base + off);
            }
            uint32_t a[4][4];
            #pragma unroll
            for (int mi = 0; mi < 4; mi++) {
                uint32_t off = (uint32_t)((a_row + mi * 16) * KS + a_coff + k16) * 2;
                LDSM4(a[mi][0], a[mi][1], a[mi][2], a[mi][3], a_hi_base + off);
            }
            #pragma unroll
            for (int mi = 0; mi < 4; mi++)
                #pragma unroll
                for (int ni = 0; ni < 4; ni++) {
                    MMA16816(acc[mi][ni], a[mi], bh[ni]);
                    MMA16816(acc[mi][ni], a[mi], bl_[ni]);
                }
            #pragma unroll
            for (int mi = 0; mi < 4; mi++) {
                uint32_t off = (uint32_t)((a_row + mi * 16) * KS + a_coff + k16) * 2;
                LDSM4(a[mi][0], a[mi][1], a[mi][2], a[mi][3], a_lo_base + off);
            }
            #pragma unroll
            for (int mi = 0; mi < 4; mi++)
                #pragma unroll
                for (int ni = 0; ni < 4; ni++)
                    MMA16816(acc[mi][ni], a[mi], bh[ni]);
        }
    }

    const int er = lane >> 2;
    const int ec = (lane & 3) * 2;
    #pragma unroll
    for (int mi = 0; mi < 4; mi++) {
        #pragma unroll
        for (int ni = 0; ni < 4; ni++) {
            int row = m0 + wm * 64 + mi * 16 + er;
            int col = n0 + wn * 32 + ni * 8 + ec;
            float b0 = bias[col], b1 = bias[col + 1];
            #pragma unroll
            for (int half = 0; half < 2; half++) {
                float x = acc[mi][ni][half * 2 + 0] + b0;
                float y = acc[mi][ni][half * 2 + 1] + b1;
                if (ACT == 1) {
                    x = 0.5f * x * (1.0f + erff(x * 0.70710678118654752f));
                    y = 0.5f * y * (1.0f + erff(y * 0.70710678118654752f));
                }
                float2 o; o.x = x; o.y = y;
                *(float2*)(C + (size_t)(row + half * 8) * N + col) = o;
            }
        }
    }
}

// ---------------- 3D RoPE on q,k in-place ([M, D] layout) ------------------
__global__ void rope_kernel(float* __restrict__ q, float* __restrict__ k,
                            const float* __restrict__ coords)
{
    int idx = blockIdx.x * blockDim.x + threadIdx.x;
    const int total = MM * NH * 16 * 3;
    if (idx >= total) return;
    int axis = idx % 3;
    int j    = (idx / 3) % 16;
    int h    = (idx / 48) % NH;
    int m    = idx / (48 * NH);

    float theta = powf(10000.0f, -(float)j / 16.0f);
    float ang = coords[(size_t)m * 3 + axis] * theta;
    float c = cosf(ang), sn = sinf(ang);

    size_t base = (size_t)m * DM + h * DH + j * 6 + axis * 2;
    float q0 = q[base], q1 = q[base + 1];
    q[base]     = q0 * c - q1 * sn;
    q[base + 1] = q0 * sn + q1 * c;
    float k0 = k[base], k1 = k[base + 1];
    k[base]     = k0 * c - k1 * sn;
    k[base + 1] = k0 * sn + k1 * c;
}

// ============ HMMA flash attention (validated R14 version) =================
#define ATQ 128
#define ATK 64
#define QST 104
#define PST 72
#define SST 66

#define AT_QHI 0
#define AT_QLO 26624
#define AT_KHI 53248
#define AT_KLO 66560
#define AT_VR  79872
#define AT_PS  93184
#define AT_SC  111616
#define AT_MI  145408
#define AT_LI  145920
#define AT_FAC 146432
#define ATTN_SMEM 146944

__global__ void __launch_bounds__(256) attn_tc(
    const float* __restrict__ q, const float* __restrict__ k,
    const float* __restrict__ v, float* __restrict__ ctx)
{
    extern __shared__ char smc[];
    uint16_t* Qhi = (uint16_t*)(smc + AT_QHI);
    uint16_t* Qlo = (uint16_t*)(smc + AT_QLO);
    uint16_t* Khi = (uint16_t*)(smc + AT_KHI);
    uint16_t* Klo = (uint16_t*)(smc + AT_KLO);
    uint16_t* Vr  = (uint16_t*)(smc + AT_VR);
    uint16_t* Ps  = (uint16_t*)(smc + AT_PS);
    float*    Sc  = (float*)(smc + AT_SC);
    float*    mi  = (float*)(smc + AT_MI);
    float*    li  = (float*)(smc + AT_LI);
    float*    fac = (float*)(smc + AT_FAC);

    const int tid  = threadIdx.x;
    const int warp = tid >> 5;
    const int lane = tid & 31;
    const int wm   = warp & 3;
    const int wn   = warp >> 2;

    const int q0 = blockIdx.x * ATQ;
    const int h  = blockIdx.y;
    const int b  = blockIdx.z;

    const uint32_t qhi_b = smem_u32(Qhi), qlo_b = smem_u32(Qlo);
    const uint32_t khi_b = smem_u32(Khi), klo_b = smem_u32(Klo);
    const uint32_t vr_b  = smem_u32(Vr),  ps_b  = smem_u32(Ps);

    const int a_row  = wm * 32 + (lane & 15);
    const int a_coff = (lane >> 4) * 8;
    const int b_row8 = (lane & 7) + ((lane >> 4) << 3);
    const int b_coff = ((lane >> 3) & 1) * 8;
    const int vt_krow = ((lane >> 3) & 1) * 8 + (lane & 7);
    const int vt_c8   = (lane >> 4) * 8;

    for (int i = tid; i < ATQ * 24; i += 256) {
        int r = i / 24, c4 = i % 24;
        float4 a = *(const float4*)(q + (size_t)(b * SS + q0 + r) * DM + h * DH + c4 * 4);
        cvt_store(Qhi, Qlo, r * QST + c4 * 4, a);
    }
    if (tid < ATQ) { mi[tid] = -1e30f; li[tid] = 0.f; }

    const float scale = 0.10206207261596575f;
    float acco[2][6][4];
    #pragma unroll
    for (int mf = 0; mf < 2; mf++)
        #pragma unroll
        for (int nf = 0; nf < 6; nf++)
            #pragma unroll
            for (int r = 0; r < 4; r++) acco[mf][nf][r] = 0.f;

    float4 kreg[6], vreg[6];
    {
        #pragma unroll
        for (int j = 0; j < 6; j++) {
            int i = j * 256 + tid;
            int r = i / 24, c4 = i % 24;
            kreg[j] = *(const float4*)(k + (size_t)(b * SS + r) * DM + h * DH + c4 * 4);
            vreg[j] = *(const float4*)(v + (size_t)(b * SS + r) * DM + h * DH + c4 * 4);
        }
    }

    for (int kt = 0; kt < SS / ATK; kt++) {
        __syncthreads();
        #pragma unroll
        for (int j = 0; j < 6; j++) {
            int i = j * 256 + tid;
            int r = i / 24, c4 = i % 24;
            cvt_store(Khi, Klo, r * QST + c4 * 4, kreg[j]);
            cvt_store1(Vr, r * QST + c4 * 4, vreg[j]);
        }
        __syncthreads();

        if (kt + 1 < SS / ATK) {
            const int kn = (kt + 1) * ATK;
            #pragma unroll
            for (int j = 0; j < 6; j++) {
                int i = j * 256 + tid;
                int r = i / 24, c4 = i % 24;
                kreg[j] = *(const float4*)(k + (size_t)(b * SS + kn + r) * DM + h * DH + c4 * 4);
                vreg[j] = *(const float4*)(v + (size_t)(b * SS + kn + r) * DM + h * DH + c4 * 4);
            }
        }

        float accs[2][4][4];
        #pragma unroll
        for (int mf = 0; mf < 2; mf++)
            #pragma unroll
            for (int nf = 0; nf < 4; nf++)
                #pragma unroll
                for (int r = 0; r < 4; r++) accs[mf][nf][r] = 0.f;

        #pragma unroll
        for (int ks = 0; ks < 6; ks++) {
            const int k16 = ks * 16;
            uint32_t bh[4][2], bl[4][2];
            #pragma unroll
            for (int p = 0; p < 2; p++) {
                uint32_t off = (uint32_t)((wn * 32 + p * 16 + b_row8) * QST + b_coff + k16) * 2;
                LDSM4(bh[p*2][0], bh[p*2][1], bh[p*2+1][0], bh[p*2+1][1], khi_b + off);
                LDSM4(bl[p*2][0], bl[p*2][1], bl[p*2+1][0], bl[p*2+1][1], klo_b + off);
            }
            uint32_t a[2][4];
            #pragma unroll
            for (int mf = 0; mf < 2; mf++) {
                uint32_t off = (uint32_t)((a_row + mf * 16) * QST + a_coff + k16) * 2;
                LDSM4(a[mf][0], a[mf][1], a[mf][2], a[mf][3], qhi_b + off);
            }
            #pragma unroll
            for (int mf = 0; mf < 2; mf++)
                #pragma unroll
                for (int nf = 0; nf < 4; nf++) {
                    MMA16816(accs[mf][nf], a[mf], bh[nf]);
                    MMA16816(accs[mf][nf], a[mf], bl[nf]);
                }
            #pragma unroll
            for (int mf = 0; mf < 2; mf++) {
                uint32_t off = (uint32_t)((a_row + mf * 16) * QST + a_coff + k16) * 2;
                LDSM4(a[mf][0], a[mf][1], a[mf][2], a[mf][3], qlo_b + off);
            }
            #pragma unroll
            for (int mf = 0; mf < 2; mf++)
                #pragma unroll
                for (int nf = 0; nf < 4; nf++)
                    MMA16816(accs[mf][nf], a[mf], bh[nf]);
        }

        {
            const int er = lane >> 2, ec = (lane & 3) * 2;
            #pragma unroll
            for (int mf = 0; mf < 2; mf++)
                #pragma unroll
                for (int nf = 0; nf < 4; nf++) {
                    int row = wm * 32 + mf * 16 + er;
                    int col = wn * 32 + nf * 8 + ec;
                    float2 o0; o0.x = accs[mf][nf][0] * scale; o0.y = accs[mf][nf][1] * scale;
                    float2 o1; o1.x = accs[mf][nf][2] * scale; o1.y = accs[mf][nf][3] * scale;
                    *(float2*)(&Sc[row * SST + col]) = o0;
                    *(float2*)(&Sc[(row + 8) * SST + col]) = o1;
                }
        }
        __syncthreads();

        {
            const int r = tid >> 1, h2 = tid & 1;
            const float* Srow = Sc + r * SST;
            float mx = -1e30f;
            #pragma unroll 8
            for (int j = 0; j < 32; j++) mx = fmaxf(mx, Srow[2 * j + h2]);
            mx = fmaxf(mx, __shfl_xor_sync(0xffffffffu, mx, 1));
            float m_old = mi[r];
            float m_new = fmaxf(m_old, mx);
            float sum = 0.f;
            #pragma unroll 8
            for (int j = 0; j < 32; j++) {
                float p = __expf(Srow[2 * j + h2] - m_new);
                sum += p;
                Ps[r * PST + 2 * j + h2] = __bfloat16_as_ushort(__float2bfloat16_rn(p));
            }
            sum += __shfl_xor_sync(0xffffffffu, sum, 1);
            if (h2 == 0) {
                float f = __expf(m_old - m_new);
                mi[r] = m_new;
                li[r] = li[r] * f + sum;
                fac[r] = f;
            }
        }
        __syncthreads();

        {
            const int er = lane >> 2;
            #pragma unroll
            for (int mf = 0; mf < 2; mf++) {
                int row = wm * 32 + mf * 16 + er;
                float f0 = fac[row], f1 = fac[row + 8];
                #pragma unroll
                for (int nf = 0; nf < 6; nf++) {
                    acco[mf][nf][0] *= f0; acco[mf][nf][1] *= f0;
                    acco[mf][nf][2] *= f1; acco[mf][nf][3] *= f1;
                }
            }
        }
        #pragma unroll
        for (int ks = 0; ks < 4; ks++) {
            const int k16 = ks * 16;
            uint32_t ap[2][4];
            #pragma unroll
            for (int mf = 0; mf < 2; mf++) {
                uint32_t off = (uint32_t)((a_row + mf * 16) * PST + a_coff + k16) * 2;
                LDSM4(ap[mf][0], ap[mf][1], ap[mf][2], ap[mf][3], ps_b + off);
            }
            uint32_t bv_[6][2];
            #pragma unroll
            for (int p = 0; p < 3; p++) {
                uint32_t off = (uint32_t)((k16 + vt_krow) * QST + wn * 48 + p * 16 + vt_c8) * 2;
                LDSM4T(bv_[p*2][0], bv_[p*2][1], bv_[p*2+1][0], bv_[p*2+1][1], vr_b + off);
            }
            #pragma unroll
            for (int mf = 0; mf < 2; mf++)
                #pragma unroll
                for (int nf = 0; nf < 6; nf++)
                    MMA16816(acco[mf][nf], ap[mf], bv_[nf]);
        }
    }

    {
        const int er = lane >> 2, ec = (lane & 3) * 2;
        #pragma unroll
        for (int mf = 0; mf < 2; mf++) {
            int row = wm * 32 + mf * 16 + er;
            float i0 = 1.0f / li[row];
            float i1 = 1.0f / li[row + 8];
            size_t m = (size_t)(b * SS + q0 + row);
            #pragma unroll
            for (int nf = 0; nf < 6; nf++) {
                int col = h * DH + wn * 48 + nf * 8 + ec;
                float2 o0; o0.x = acco[mf][nf][0] * i0; o0.y = acco[mf][nf][1] * i0;
                float2 o1; o1.x = acco[mf][nf][2] * i1; o1.y = acco[mf][nf][3] * i1;
                *(float2*)(ctx + m * DM + col) = o0;
                *(float2*)(ctx + (m + 8) * DM + col) = o1;
            }
        }
    }
}

// ---------------- residual add + LayerNorm (one block per row) -------------
__device__ __forceinline__ float block_sum256(float val, float* red) {
    #pragma unroll
    for (int o = 16; o > 0; o >>= 1)
        val += __shfl_xor_sync(0xffffffffu, val, o);
    int w = threadIdx.x >> 5;
    if ((threadIdx.x & 31) == 0) red[w] = val;
    __syncthreads();
    if (threadIdx.x < 32) {
        float vv = (threadIdx.x < 8) ? red[threadIdx.x] : 0.f;
        #pragma unroll
        for (int o = 4; o > 0; o >>= 1)
            vv += __shfl_xor_sync(0xffffffffu, vv, o);
        if (threadIdx.x == 0) red[0] = vv;
    }
    __syncthreads();
    float r = red[0];
    __syncthreads();
    return r;
}

__global__ void __launch_bounds__(256) add_ln_kernel(
    const float* __restrict__ x, const float* __restrict__ y,
    const float* __restrict__ g, const float* __restrict__ be,
    float* __restrict__ out)
{
    __shared__ float red[32];
    size_t m = blockIdx.x;
    const float* xr = x + m * DM;
    const float* yr = y + m * DM;

    float v[3];
    float s = 0.f;
    #pragma unroll
    for (int i = 0; i < 3; i++) {
        int d = threadIdx.x + i * 256;
        v[i] = xr[d] + yr[d];
        s += v[i];
    }
    float mean = block_sum256(s, red) * (1.0f / DM);
    float sq = 0.f;
    #pragma unroll
    for (int i = 0; i < 3; i++) {
        float dd = v[i] - mean;
        sq += dd * dd;
    }
    float var = block_sum256(sq, red) * (1.0f / DM);
    float inv = rsqrtf(var + 1e-5f);
    #pragma unroll
    for (int i = 0; i < 3; i++) {
        int d = threadIdx.x + i * 256;
        out[m * DM + d] = (v[i] - mean) * inv * g[d] + be[d];
    }
}

// ---------------- launch ---------------------------------------------------
extern "C" void kernel_launch(void* const* d_in, const int* in_sizes, int n_in,
                              void* d_out, int out_size)
{
    const float* src    = (const float*)d_in[0];
    const float* coords = (const float*)d_in[1];
    const float* Wq = (const float*)d_in[2];
    const float* bq = (const float*)d_in[3];
    const float* Wk = (const float*)d_in[4];
    const float* bk = (const float*)d_in[5];
    const float* Wv = (const float*)d_in[6];
    const float* bv = (const float*)d_in[7];
    const float* Wo = (const float*)d_in[8];
    const float* bo = (const float*)d_in[9];
    const float* W1 = (const float*)d_in[10];
    const float* b1 = (const float*)d_in[11];
    const float* W2 = (const float*)d_in[12];
    const float* b2 = (const float*)d_in[13];
    const float* g1  = (const float*)d_in[14];
    const float* be1 = (const float*)d_in[15];
    const float* g2  = (const float*)d_in[16];
    const float* be2 = (const float*)d_in[17];
    float* out = (float*)d_out;

    float *q, *k, *v, *ctx, *t1, *src2, *ffh;
    uint16_t *whi, *wlo;
    cudaGetSymbolAddress((void**)&q,    g_q);
    cudaGetSymbolAddress((void**)&k,    g_k);
    cudaGetSymbolAddress((void**)&v,    g_v);
    cudaGetSymbolAddress((void**)&ctx,  g_ctx);
    cudaGetSymbolAddress((void**)&t1,   g_t1);
    cudaGetSymbolAddress((void**)&src2, g_src2);
    cudaGetSymbolAddress((void**)&ffh,  g_ffh);
    cudaGetSymbolAddress((void**)&whi,  g_whi);
    cudaGetSymbolAddress((void**)&wlo,  g_wlo);

    // preconvert weights to hi/lo bf16 (bit-identical to in-loop conversion)
    {
        const int n4q = 589824 / 4, n4f = 2359296 / 4;
        cvt_w_kernel<<<(n4q + 255) / 256, 256>>>(Wq, whi + OWQ, wlo + OWQ, n4q);
        cvt_w_kernel<<<(n4q + 255) / 256, 256>>>(Wk, whi + OWK, wlo + OWK, n4q);
        cvt_w_kernel<<<(n4q + 255) / 256, 256>>>(Wv, whi + OWV, wlo + OWV, n4q);
        cvt_w_kernel<<<(n4q + 255) / 256, 256>>>(Wo, whi + OWO, wlo + OWO, n4q);
        cvt_w_kernel<<<(n4f + 255) / 256, 256>>>(W1, whi + OW1, wlo + OW1, n4f);
        cvt_w_kernel<<<(n4f + 255) / 256, 256>>>(W2, whi + OW2, wlo + OW2, n4f);
    }

    dim3 g768(DM / 128, MM / 128);     // (6, 64)
    dim3 gff(DFF / 128, MM / 128);     // (24, 64)

    // QKV projections
    gemm_tc<0><<<g768, 256>>>(src, whi + OWQ, wlo + OWQ, bq, q, MM, DM, DM);
    gemm_tc<0><<<g768, 256>>>(src, whi + OWK, wlo + OWK, bk, k, MM, DM, DM);
    gemm_tc<0><<<g768, 256>>>(src, whi + OWV, wlo + OWV, bv, v, MM, DM, DM);

    // RoPE on q, k
    {
        int total = MM * NH * 16 * 3;
        rope_kernel<<<(total + 255) / 256, 256>>>(q, k, coords);
    }

    // attention (HMMA, pipelined, trans-V)
    cudaFuncSetAttribute((const void*)attn_tc,
                         cudaFuncAttributeMaxDynamicSharedMemorySize, ATTN_SMEM);
    attn_tc<<<dim3(SS / ATQ, NH, BB), 256, ATTN_SMEM>>>(q, k, v, ctx);

    // output projection + residual + LN1
    gemm_tc<0><<<g768, 256>>>(ctx, whi + OWO, wlo + OWO, bo, t1, MM, DM, DM);
    add_ln_kernel<<<MM, 256>>>(src, t1, g1, be1, src2);

    // FFN
    gemm_tc<1><<<gff, 256>>>(src2, whi + OW1, wlo + OW1, b1, ffh, MM, DFF, DM);
    gemm_tc<0><<<g768, 256>>>(ffh, whi + OW2, wlo + OW2, b2, t1, MM, DM, DFF);
    add_ln_kernel<<<MM, 256>>>(src2, t1, g2, be2, out);
}

// round 16
// speedup vs baseline: 3.3417x; 1.1540x over previous
#include <cuda_runtime.h>
#include <cuda_bf16.h>
#include <math.h>
#include <stddef.h>
#include <stdint.h>

#define BB 4
#define SS 2048
#define DM 768
#define NH 8
#define DH 96
#define DFF 3072
#define MM (BB*SS)   /* 8192 rows */

// weight offsets in the preconverted hi/lo buffers
#define OWQ 0
#define OWK 589824
#define OWV 1179648
#define OWO 1769472
#define OW1 2359296
#define OW2 4718592
#define NWTOT 7077888

// ---------------- scratch (device globals: allocation-free) ----------------
__device__ float g_q[MM*DM];
__device__ float g_k[MM*DM];
__device__ float g_v[MM*DM];
__device__ float g_ctx[MM*DM];
__device__ float g_t1[MM*DM];
__device__ float g_src2[MM*DM];
__device__ float g_ffh[(size_t)MM*DFF];
__device__ uint16_t g_whi[NWTOT];
__device__ uint16_t g_wlo[NWTOT];

// ================= helpers =================================================
static __device__ __forceinline__ uint32_t smem_u32(const void* p) {
    uint32_t a;
    asm("{ .reg .u64 t; cvta.to.shared.u64 t, %1; cvt.u32.u64 %0, t; }"
        : "=r"(a) : "l"(p));
    return a;
}

#define LDSM4(R0,R1,R2,R3,addr) \
    asm volatile("ldmatrix.sync.aligned.m8n8.x4.shared.b16 {%0,%1,%2,%3}, [%4];" \
        : "=r"(R0),"=r"(R1),"=r"(R2),"=r"(R3) : "r"(addr))

#define LDSM4T(R0,R1,R2,R3,addr) \
    asm volatile("ldmatrix.sync.aligned.m8n8.x4.trans.shared.b16 {%0,%1,%2,%3}, [%4];" \
        : "=r"(R0),"=r"(R1),"=r"(R2),"=r"(R3) : "r"(addr))

#define MMA16816(d, a, b) \
    asm volatile("mma.sync.aligned.m16n8k16.row.col.f32.bf16.bf16.f32 " \
        "{%0,%1,%2,%3}, {%4,%5,%6,%7}, {%8,%9}, {%0,%1,%2,%3};" \
        : "+f"((d)[0]), "+f"((d)[1]), "+f"((d)[2]), "+f"((d)[3]) \
        : "r"((a)[0]), "r"((a)[1]), "r"((a)[2]), "r"((a)[3]), \
          "r"((b)[0]), "r"((b)[1]))

// convert one float4 to hi/lo bf16x2 pairs and store 8B each
static __device__ __forceinline__ void cvt_store(
    uint16_t* __restrict__ hi, uint16_t* __restrict__ lo, int eoff, float4 a)
{
    __nv_bfloat16 hx = __float2bfloat16_rn(a.x);
    __nv_bfloat16 hy = __float2bfloat16_rn(a.y);
    __nv_bfloat16 hz = __float2bfloat16_rn(a.z);
    __nv_bfloat16 hw = __float2bfloat16_rn(a.w);
    __nv_bfloat162 h0; h0.x = hx; h0.y = hy;
    __nv_bfloat162 h1; h1.x = hz; h1.y = hw;
    __nv_bfloat162 l0 = __floats2bfloat162_rn(a.x - __bfloat162float(hx),
                                              a.y - __bfloat162float(hy));
    __nv_bfloat162 l1 = __floats2bfloat162_rn(a.z - __bfloat162float(hz),
                                              a.w - __bfloat162float(hw));
    uint2 hv; hv.x = *(uint32_t*)&h0; hv.y = *(uint32_t*)&h1;
    uint2 lv; lv.x = *(uint32_t*)&l0; lv.y = *(uint32_t*)&l1;
    *(uint2*)(hi + eoff) = hv;
    *(uint2*)(lo + eoff) = lv;
}

// pack float4 -> 4 bf16 (8B)
static __device__ __forceinline__ void cvt_store1(
    uint16_t* __restrict__ dst, int eoff, float4 a)
{
    __nv_bfloat162 p0 = __floats2bfloat162_rn(a.x, a.y);
    __nv_bfloat162 p1 = __floats2bfloat162_rn(a.z, a.w);
    uint2 pv; pv.x = *(uint32_t*)&p0; pv.y = *(uint32_t*)&p1;
    *(uint2*)(dst + eoff) = pv;
}

static __device__ __forceinline__ uint32_t pack_bf2(float x, float y) {
    __nv_bfloat162 p = __floats2bfloat162_rn(x, y);
    return *(uint32_t*)&p;
}

// ---------------- weight preconversion: fp32 -> hi/lo bf16 -----------------
__global__ void cvt_w_kernel(const float* __restrict__ w,
                             uint16_t* __restrict__ hi,
                             uint16_t* __restrict__ lo, int n4)
{
    int i = blockIdx.x * blockDim.x + threadIdx.x;
    if (i >= n4) return;
    float4 a = ((const float4*)w)[i];
    cvt_store(hi, lo, i * 4, a);
}

// ============ HMMA GEMM (R15-validated) ====================================
#define KS 40

template<int ACT>
__global__ void __launch_bounds__(256) gemm_tc(
    const float* __restrict__ A,
    const uint16_t* __restrict__ Bhi_g, const uint16_t* __restrict__ Blo_g,
    const float* __restrict__ bias, float* __restrict__ C,
    int M, int N, int K)
{
    __shared__ __align__(16) uint16_t As_hi[128*KS];
    __shared__ __align__(16) uint16_t As_lo[128*KS];
    __shared__ __align__(16) uint16_t Bs_hi[128*KS];
    __shared__ __align__(16) uint16_t Bs_lo[128*KS];

    const int tid  = threadIdx.x;
    const int warp = tid >> 5;
    const int lane = tid & 31;
    const int wm   = warp & 1;
    const int wn   = warp >> 1;

    const int m0 = blockIdx.y * 128;
    const int n0 = blockIdx.x * 128;
    const float* Ab = A + (size_t)m0 * K;
    const uint16_t* Bb_hi = Bhi_g + (size_t)n0 * K;
    const uint16_t* Bb_lo = Blo_g + (size_t)n0 * K;

    const int l_row = tid >> 3;
    const int l_c4  = tid & 7;
    const int bl_row = tid >> 2;
    const int bl_c   = (tid & 3) * 8;

    const uint32_t a_hi_base = smem_u32(As_hi);
    const uint32_t a_lo_base = smem_u32(As_lo);
    const uint32_t b_hi_base = smem_u32(Bs_hi);
    const uint32_t b_lo_base = smem_u32(Bs_lo);
    const int a_row  = wm * 64 + (lane & 15);
    const int a_coff = (lane >> 4) * 8;
    const int b_row  = wn * 32 + (lane & 7) + ((lane >> 4) << 3);
    const int b_coff = ((lane >> 3) & 1) * 8;

    float acc[4][4][4];
    #pragma unroll
    for (int mi = 0; mi < 4; mi++)
        #pragma unroll
        for (int ni = 0; ni < 4; ni++)
            #pragma unroll
            for (int r = 0; r < 4; r++) acc[mi][ni][r] = 0.f;

    float4 av[4];
    uint4 ph[2], pl[2];
    #pragma unroll
    for (int i = 0; i < 4; i++)
        av[i] = *(const float4*)(Ab + (size_t)(l_row + i * 32) * K + l_c4 * 4);
    #pragma unroll
    for (int j = 0; j < 2; j++) {
        ph[j] = *(const uint4*)(Bb_hi + (size_t)(bl_row + j * 64) * K + bl_c);
        pl[j] = *(const uint4*)(Bb_lo + (size_t)(bl_row + j * 64) * K + bl_c);
    }

    const int T = K >> 5;
    for (int t = 0; t < T; t++) {
        __syncthreads();
        #pragma unroll
        for (int i = 0; i < 4; i++) {
            int eoff = (l_row + i * 32) * KS + l_c4 * 4;
            cvt_store(As_hi, As_lo, eoff, av[i]);
        }
        #pragma unroll
        for (int j = 0; j < 2; j++) {
            uint32_t boff = (uint32_t)((bl_row + j * 64) * KS + bl_c) * 2;
            *(uint4*)((char*)Bs_hi + boff) = ph[j];
            *(uint4*)((char*)Bs_lo + boff) = pl[j];
        }
        __syncthreads();

        if (t + 1 < T) {
            const int kn = (t + 1) << 5;
            #pragma unroll
            for (int i = 0; i < 4; i++)
                av[i] = *(const float4*)(Ab + (size_t)(l_row + i * 32) * K + kn + l_c4 * 4);
            #pragma unroll
            for (int j = 0; j < 2; j++) {
                ph[j] = *(const uint4*)(Bb_hi + (size_t)(bl_row + j * 64) * K + kn + bl_c);
                pl[j] = *(const uint4*)(Bb_lo + (size_t)(bl_row + j * 64) * K + kn + bl_c);
            }
        }

        #pragma unroll
        for (int kh = 0; kh < 2; kh++) {
            const int k16 = kh * 16;
            uint32_t bh[4][2], bl_[4][2];
            #pragma unroll
            for (int p = 0; p < 2; p++) {
                uint32_t off = (uint32_t)((b_row + p * 16) * KS + b_coff + k16) * 2;
                LDSM4(bh[p*2][0], bh[p*2][1], bh[p*2+1][0], bh[p*2+1][1], b_hi_base + off);
                LDSM4(bl_[p*2][0], bl_[p*2][1], bl_[p*2+1][0], bl_[p*2+1][1], b_lo_base + off);
            }
            uint32_t a[4][4];
            #pragma unroll
            for (int mi = 0; mi < 4; mi++) {
                uint32_t off = (uint32_t)((a_row + mi * 16) * KS + a_coff + k16) * 2;
                LDSM4(a[mi][0], a[mi][1], a[mi][2], a[mi][3], a_hi_base + off);
            }
            #pragma unroll
            for (int mi = 0; mi < 4; mi++)
                #pragma unroll
                for (int ni = 0; ni < 4; ni++) {
                    MMA16816(acc[mi][ni], a[mi], bh[ni]);
                    MMA16816(acc[mi][ni], a[mi], bl_[ni]);
                }
            #pragma unroll
            for (int mi = 0; mi < 4; mi++) {
                uint32_t off = (uint32_t)((a_row + mi * 16) * KS + a_coff + k16) * 2;
                LDSM4(a[mi][0], a[mi][1], a[mi][2], a[mi][3], a_lo_base + off);
            }
            #pragma unroll
            for (int mi = 0; mi < 4; mi++)
                #pragma unroll
                for (int ni = 0; ni < 4; ni++)
                    MMA16816(acc[mi][ni], a[mi], bh[ni]);
        }
    }

    const int er = lane >> 2;
    const int ec = (lane & 3) * 2;
    #pragma unroll
    for (int mi = 0; mi < 4; mi++) {
        #pragma unroll
        for (int ni = 0; ni < 4; ni++) {
            int row = m0 + wm * 64 + mi * 16 + er;
            int col = n0 + wn * 32 + ni * 8 + ec;
            float b0 = bias[col], b1 = bias[col + 1];
            #pragma unroll
            for (int half = 0; half < 2; half++) {
                float x = acc[mi][ni][half * 2 + 0] + b0;
                float y = acc[mi][ni][half * 2 + 1] + b1;
                if (ACT == 1) {
                    x = 0.5f * x * (1.0f + erff(x * 0.70710678118654752f));
                    y = 0.5f * y * (1.0f + erff(y * 0.70710678118654752f));
                }
                float2 o; o.x = x; o.y = y;
                *(float2*)(C + (size_t)(row + half * 8) * N + col) = o;
            }
        }
    }
}

// ---------------- 3D RoPE on q,k in-place ([M, D] layout) ------------------
__global__ void rope_kernel(float* __restrict__ q, float* __restrict__ k,
                            const float* __restrict__ coords)
{
    int idx = blockIdx.x * blockDim.x + threadIdx.x;
    const int total = MM * NH * 16 * 3;
    if (idx >= total) return;
    int axis = idx % 3;
    int j    = (idx / 3) % 16;
    int h    = (idx / 48) % NH;
    int m    = idx / (48 * NH);

    float theta = powf(10000.0f, -(float)j / 16.0f);
    float ang = coords[(size_t)m * 3 + axis] * theta;
    float c = cosf(ang), sn = sinf(ang);

    size_t base = (size_t)m * DM + h * DH + j * 6 + axis * 2;
    float q0 = q[base], q1 = q[base + 1];
    q[base]     = q0 * c - q1 * sn;
    q[base + 1] = q0 * sn + q1 * c;
    float k0 = k[base], k1 = k[base + 1];
    k[base]     = k0 * c - k1 * sn;
    k[base + 1] = k0 * sn + k1 * c;
}

// ============ HMMA flash attention, register softmax =======================
// 256 threads = 8 warps; warp w owns q-rows w*16..w*16+15 x ALL 64 keys.
// QK: hi/lo bf16 split. Softmax fully in registers (2 shuffles + per-lane m/l).
// P packs directly from score D-frags into PV A-frags (identical layout).
#define ATQ 128
#define ATK 64
#define QST 104   /* 208B = 13x16B odd -> conflict-free */

#define AT_QHI 0
#define AT_QLO 26624
#define AT_KHI 53248
#define AT_KLO 66560
#define AT_VR  79872
#define ATTN_SMEM 93184

__global__ void __launch_bounds__(256) attn_tc(
    const float* __restrict__ q, const float* __restrict__ k,
    const float* __restrict__ v, float* __restrict__ ctx)
{
    extern __shared__ char smc[];
    uint16_t* Qhi = (uint16_t*)(smc + AT_QHI);
    uint16_t* Qlo = (uint16_t*)(smc + AT_QLO);
    uint16_t* Khi = (uint16_t*)(smc + AT_KHI);
    uint16_t* Klo = (uint16_t*)(smc + AT_KLO);
    uint16_t* Vr  = (uint16_t*)(smc + AT_VR);

    const int tid  = threadIdx.x;
    const int warp = tid >> 5;
    const int lane = tid & 31;

    const int q0 = blockIdx.x * ATQ;
    const int h  = blockIdx.y;
    const int b  = blockIdx.z;

    const uint32_t qhi_b = smem_u32(Qhi), qlo_b = smem_u32(Qlo);
    const uint32_t khi_b = smem_u32(Khi), klo_b = smem_u32(Klo);
    const uint32_t vr_b  = smem_u32(Vr);

    // ldmatrix lane addressing
    const int a_row  = warp * 16 + (lane & 15);   // A operand rows (q)
    const int a_coff = (lane >> 4) * 8;
    const int b_row8 = (lane & 7) + ((lane >> 4) << 3);
    const int b_coff = ((lane >> 3) & 1) * 8;
    const int vt_krow = ((lane >> 3) & 1) * 8 + (lane & 7);
    const int vt_c8   = (lane >> 4) * 8;
    const int er = lane >> 2;        // D/A-frag row within 16
    const int ec = (lane & 3) * 2;   // D/A-frag col pair

    // load Q tile once (hi/lo bf16)
    for (int i = tid; i < ATQ * 24; i += 256) {
        int r = i / 24, c4 = i % 24;
        float4 a = *(const float4*)(q + (size_t)(b * SS + q0 + r) * DM + h * DH + c4 * 4);
        cvt_store(Qhi, Qlo, r * QST + c4 * 4, a);
    }

    const float scale = 0.10206207261596575f;   // 1/sqrt(96)
    float acco[12][4];
    #pragma unroll
    for (int nf = 0; nf < 12; nf++)
        #pragma unroll
        for (int r = 0; r < 4; r++) acco[nf][r] = 0.f;
    float mi0 = -1e30f, mi1 = -1e30f, li0 = 0.f, li1 = 0.f;

    // prefetch K/V tile 0 into registers
    float4 kreg[6], vreg[6];
    #pragma unroll
    for (int j = 0; j < 6; j++) {
        int i = j * 256 + tid;
        int r = i / 24, c4 = i % 24;
        kreg[j] = *(const float4*)(k + (size_t)(b * SS + r) * DM + h * DH + c4 * 4);
        vreg[j] = *(const float4*)(v + (size_t)(b * SS + r) * DM + h * DH + c4 * 4);
    }

    for (int kt = 0; kt < SS / ATK; kt++) {
        __syncthreads();   // prior tile's K/V smem reads done; Q visible on kt=0
        #pragma unroll
        for (int j = 0; j < 6; j++) {
            int i = j * 256 + tid;
            int r = i / 24, c4 = i % 24;
            cvt_store(Khi, Klo, r * QST + c4 * 4, kreg[j]);
            cvt_store1(Vr, r * QST + c4 * 4, vreg[j]);
        }
        __syncthreads();

        // issue next tile's gmem loads (latency hides behind QK/softmax/PV)
        if (kt + 1 < SS / ATK) {
            const int kn = (kt + 1) * ATK;
            #pragma unroll
            for (int j = 0; j < 6; j++) {
                int i = j * 256 + tid;
                int r = i / 24, c4 = i % 24;
                kreg[j] = *(const float4*)(k + (size_t)(b * SS + kn + r) * DM + h * DH + c4 * 4);
                vreg[j] = *(const float4*)(v + (size_t)(b * SS + kn + r) * DM + h * DH + c4 * 4);
            }
        }

        // ---- scores = Q K^T (hi/lo split), warp tile 16x64 ----
        float accs[8][4];
        #pragma unroll
        for (int nf = 0; nf < 8; nf++)
            #pragma unroll
            for (int r = 0; r < 4; r++) accs[nf][r] = 0.f;

        #pragma unroll
        for (int ks = 0; ks < 6; ks++) {
            const int k16 = ks * 16;
            uint32_t aqh[4], aql[4];
            {
                uint32_t off = (uint32_t)(a_row * QST + a_coff + k16) * 2;
                LDSM4(aqh[0], aqh[1], aqh[2], aqh[3], qhi_b + off);
                LDSM4(aql[0], aql[1], aql[2], aql[3], qlo_b + off);
            }
            #pragma unroll
            for (int p = 0; p < 4; p++) {
                uint32_t off = (uint32_t)((p * 16 + b_row8) * QST + b_coff + k16) * 2;
                uint32_t bh[2][2], bl[2][2];
                LDSM4(bh[0][0], bh[0][1], bh[1][0], bh[1][1], khi_b + off);
                LDSM4(bl[0][0], bl[0][1], bl[1][0], bl[1][1], klo_b + off);
                #pragma unroll
                for (int u = 0; u < 2; u++) {
                    MMA16816(accs[2*p+u], aqh, bh[u]);
                    MMA16816(accs[2*p+u], aqh, bl[u]);
                    MMA16816(accs[2*p+u], aql, bh[u]);
                }
            }
        }

        // ---- register softmax (rows er and er+8; 4 lanes share a row) ----
        #pragma unroll
        for (int nf = 0; nf < 8; nf++)
            #pragma unroll
            for (int r = 0; r < 4; r++) accs[nf][r] *= scale;

        float mx0 = -1e30f, mx1 = -1e30f;
        #pragma unroll
        for (int nf = 0; nf < 8; nf++) {
            mx0 = fmaxf(mx0, fmaxf(accs[nf][0], accs[nf][1]));
            mx1 = fmaxf(mx1, fmaxf(accs[nf][2], accs[nf][3]));
        }
        mx0 = fmaxf(mx0, __shfl_xor_sync(0xffffffffu, mx0, 1));
        mx0 = fmaxf(mx0, __shfl_xor_sync(0xffffffffu, mx0, 2));
        mx1 = fmaxf(mx1, __shfl_xor_sync(0xffffffffu, mx1, 1));
        mx1 = fmaxf(mx1, __shfl_xor_sync(0xffffffffu, mx1, 2));

        float mn0 = fmaxf(mi0, mx0), mn1 = fmaxf(mi1, mx1);
        float fac0 = __expf(mi0 - mn0), fac1 = __expf(mi1 - mn1);
        mi0 = mn0; mi1 = mn1;

        float sum0 = 0.f, sum1 = 0.f;
        #pragma unroll
        for (int nf = 0; nf < 8; nf++) {
            accs[nf][0] = __expf(accs[nf][0] - mn0);
            accs[nf][1] = __expf(accs[nf][1] - mn0);
            accs[nf][2] = __expf(accs[nf][2] - mn1);
            accs[nf][3] = __expf(accs[nf][3] - mn1);
            sum0 += accs[nf][0] + accs[nf][1];
            sum1 += accs[nf][2] + accs[nf][3];
        }
        sum0 += __shfl_xor_sync(0xffffffffu, sum0, 1);
        sum0 += __shfl_xor_sync(0xffffffffu, sum0, 2);
        sum1 += __shfl_xor_sync(0xffffffffu, sum1, 1);
        sum1 += __shfl_xor_sync(0xffffffffu, sum1, 2);
        li0 = li0 * fac0 + sum0;
        li1 = li1 * fac1 + sum1;

        // rescale accumulators
        #pragma unroll
        for (int nf = 0; nf < 12; nf++) {
            acco[nf][0] *= fac0; acco[nf][1] *= fac0;
            acco[nf][2] *= fac1; acco[nf][3] *= fac1;
        }

        // ---- acc += P V : P packs directly from score registers ----
        #pragma unroll
        for (int ks = 0; ks < 4; ks++) {
            uint32_t ap[4];
            ap[0] = pack_bf2(accs[2*ks][0],   accs[2*ks][1]);
            ap[1] = pack_bf2(accs[2*ks][2],   accs[2*ks][3]);
            ap[2] = pack_bf2(accs[2*ks+1][0], accs[2*ks+1][1]);
            ap[3] = pack_bf2(accs[2*ks+1][2], accs[2*ks+1][3]);
            #pragma unroll
            for (int j = 0; j < 6; j++) {
                uint32_t off = (uint32_t)((ks * 16 + vt_krow) * QST + j * 16 + vt_c8) * 2;
                uint32_t bv_[2][2];
                LDSM4T(bv_[0][0], bv_[0][1], bv_[1][0], bv_[1][1], vr_b + off);
                MMA16816(acco[2*j+0], ap, bv_[0]);
                MMA16816(acco[2*j+1], ap, bv_[1]);
            }
        }
    }

    // epilogue: normalize and write ctx
    {
        float i0 = 1.0f / li0;
        float i1 = 1.0f / li1;
        size_t m = (size_t)(b * SS + q0 + warp * 16 + er);
        #pragma unroll
        for (int nf = 0; nf < 12; nf++) {
            int col = h * DH + nf * 8 + ec;
            float2 o0; o0.x = acco[nf][0] * i0; o0.y = acco[nf][1] * i0;
            float2 o1; o1.x = acco[nf][2] * i1; o1.y = acco[nf][3] * i1;
            *(float2*)(ctx + m * DM + col) = o0;
            *(float2*)(ctx + (m + 8) * DM + col) = o1;
        }
    }
}

// ---------------- residual add + LayerNorm (one block per row) -------------
__device__ __forceinline__ float block_sum256(float val, float* red) {
    #pragma unroll
    for (int o = 16; o > 0; o >>= 1)
        val += __shfl_xor_sync(0xffffffffu, val, o);
    int w = threadIdx.x >> 5;
    if ((threadIdx.x & 31) == 0) red[w] = val;
    __syncthreads();
    if (threadIdx.x < 32) {
        float vv = (threadIdx.x < 8) ? red[threadIdx.x] : 0.f;
        #pragma unroll
        for (int o = 4; o > 0; o >>= 1)
            vv += __shfl_xor_sync(0xffffffffu, vv, o);
        if (threadIdx.x == 0) red[0] = vv;
    }
    __syncthreads();
    float r = red[0];
    __syncthreads();
    return r;
}

__global__ void __launch_bounds__(256) add_ln_kernel(
    const float* __restrict__ x, const float* __restrict__ y,
    const float* __restrict__ g, const float* __restrict__ be,
    float* __restrict__ out)
{
    __shared__ float red[32];
    size_t m = blockIdx.x;
    const float* xr = x + m * DM;
    const float* yr = y + m * DM;

    float v[3];
    float s = 0.f;
    #pragma unroll
    for (int i = 0; i < 3; i++) {
        int d = threadIdx.x + i * 256;
        v[i] = xr[d] + yr[d];
        s += v[i];
    }
    float mean = block_sum256(s, red) * (1.0f / DM);
    float sq = 0.f;
    #pragma unroll
    for (int i = 0; i < 3; i++) {
        float dd = v[i] - mean;
        sq += dd * dd;
    }
    float var = block_sum256(sq, red) * (1.0f / DM);
    float inv = rsqrtf(var + 1e-5f);
    #pragma unroll
    for (int i = 0; i < 3; i++) {
        int d = threadIdx.x + i * 256;
        out[m * DM + d] = (v[i] - mean) * inv * g[d] + be[d];
    }
}

// ---------------- launch ---------------------------------------------------
extern "C" void kernel_launch(void* const* d_in, const int* in_sizes, int n_in,
                              void* d_out, int out_size)
{
    const float* src    = (const float*)d_in[0];
    const float* coords = (const float*)d_in[1];
    const float* Wq = (const float*)d_in[2];
    const float* bq = (const float*)d_in[3];
    const float* Wk = (const float*)d_in[4];
    const float* bk = (const float*)d_in[5];
    const float* Wv = (const float*)d_in[6];
    const float* bv = (const float*)d_in[7];
    const float* Wo = (const float*)d_in[8];
    const float* bo = (const float*)d_in[9];
    const float* W1 = (const float*)d_in[10];
    const float* b1 = (const float*)d_in[11];
    const float* W2 = (const float*)d_in[12];
    const float* b2 = (const float*)d_in[13];
    const float* g1  = (const float*)d_in[14];
    const float* be1 = (const float*)d_in[15];
    const float* g2  = (const float*)d_in[16];
    const float* be2 = (const float*)d_in[17];
    float* out = (float*)d_out;

    float *q, *k, *v, *ctx, *t1, *src2, *ffh;
    uint16_t *whi, *wlo;
    cudaGetSymbolAddress((void**)&q,    g_q);
    cudaGetSymbolAddress((void**)&k,    g_k);
    cudaGetSymbolAddress((void**)&v,    g_v);
    cudaGetSymbolAddress((void**)&ctx,  g_ctx);
    cudaGetSymbolAddress((void**)&t1,   g_t1);
    cudaGetSymbolAddress((void**)&src2, g_src2);
    cudaGetSymbolAddress((void**)&ffh,  g_ffh);
    cudaGetSymbolAddress((void**)&whi,  g_whi);
    cudaGetSymbolAddress((void**)&wlo,  g_wlo);

    // preconvert weights to hi/lo bf16
    {
        const int n4q = 589824 / 4, n4f = 2359296 / 4;
        cvt_w_kernel<<<(n4q + 255) / 256, 256>>>(Wq, whi + OWQ, wlo + OWQ, n4q);
        cvt_w_kernel<<<(n4q + 255) / 256, 256>>>(Wk, whi + OWK, wlo + OWK, n4q);
        cvt_w_kernel<<<(n4q + 255) / 256, 256>>>(Wv, whi + OWV, wlo + OWV, n4q);
        cvt_w_kernel<<<(n4q + 255) / 256, 256>>>(Wo, whi + OWO, wlo + OWO, n4q);
        cvt_w_kernel<<<(n4f + 255) / 256, 256>>>(W1, whi + OW1, wlo + OW1, n4f);
        cvt_w_kernel<<<(n4f + 255) / 256, 256>>>(W2, whi + OW2, wlo + OW2, n4f);
    }

    dim3 g768(DM / 128, MM / 128);     // (6, 64)
    dim3 gff(DFF / 128, MM / 128);     // (24, 64)

    // QKV projections
    gemm_tc<0><<<g768, 256>>>(src, whi + OWQ, wlo + OWQ, bq, q, MM, DM, DM);
    gemm_tc<0><<<g768, 256>>>(src, whi + OWK, wlo + OWK, bk, k, MM, DM, DM);
    gemm_tc<0><<<g768, 256>>>(src, whi + OWV, wlo + OWV, bv, v, MM, DM, DM);

    // RoPE on q, k
    {
        int total = MM * NH * 16 * 3;
        rope_kernel<<<(total + 255) / 256, 256>>>(q, k, coords);
    }

    // attention (HMMA, pipelined, register softmax)
    cudaFuncSetAttribute((const void*)attn_tc,
                         cudaFuncAttributeMaxDynamicSharedMemorySize, ATTN_SMEM);
    attn_tc<<<dim3(SS / ATQ, NH, BB), 256, ATTN_SMEM>>>(q, k, v, ctx);

    // output projection + residual + LN1
    gemm_tc<0><<<g768, 256>>>(ctx, whi + OWO, wlo + OWO, bo, t1, MM, DM, DM);
    add_ln_kernel<<<MM, 256>>>(src, t1, g1, be1, src2);

    // FFN
    gemm_tc<1><<<gff, 256>>>(src2, whi + OW1, wlo + OW1, b1, ffh, MM, DFF, DM);
    gemm_tc<0><<<g768, 256>>>(ffh, whi + OW2, wlo + OW2, b2, t1, MM, DM, DFF);
    add_ln_kernel<<<MM, 256>>>(src2, t1, g2, be2, out);
}